// round 9
// baseline (speedup 1.0000x reference)
#include <cuda_runtime.h>
#include <cuda_bf16.h>
#include <cstdint>

#define BATCH 2
#define C 128
#define H 96
#define W 96
#define HEADS 4
#define DHEAD 32
#define PAD 2
#define INNER 128
#define HW (H * W)
#define HP (H + 2 * PAD)
#define WP (W + 2 * PAD)
#define NTILES (HW / 128)   // 72

typedef unsigned long long u64;

// fp32 scratch
__device__ float g_q[(size_t)BATCH * HW * INNER];          // [b][p][inner]
__device__ float g_kpad[(size_t)BATCH * HP * WP * INNER];  // [b][yp][xp][inner]
__device__ float g_vpad[(size_t)BATCH * HP * WP * INNER];

// bf16 hi/lo operand images
__device__ __nv_bfloat16 g_xhi[(size_t)BATCH * HW * C];    // [b][p][c]
__device__ __nv_bfloat16 g_xlo[(size_t)BATCH * HW * C];
__device__ __nv_bfloat16 g_whi[4 * C * INNER];             // [mat][o][c]
__device__ __nv_bfloat16 g_wlo[4 * C * INNER];
__device__ __nv_bfloat16 g_ohi[(size_t)BATCH * HW * INNER];// [b][p][inner]
__device__ __nv_bfloat16 g_olo[(size_t)BATCH * HW * INNER];

#define FFMA2(d, a, b) \
    asm("fma.rn.f32x2 %0, %1, %2, %0;" : "+l"(d) : "l"(a), "l"(b))
#define PACK2(d, s) \
    asm("mov.b64 %0, {%1, %1};" : "=l"(d) : "f"(s))

__device__ __forceinline__ void cp16(uint32_t smem, const void* g) {
    asm volatile("cp.async.cg.shared.global [%0], [%1], 16;" :: "r"(smem), "l"(g));
}
#define CP_COMMIT() asm volatile("cp.async.commit_group;")
#define CP_WAIT(n)  asm volatile("cp.async.wait_group %0;" :: "n"(n))

__device__ __forceinline__ uint32_t smem_u32(const void* p) {
    uint32_t a;
    asm("{ .reg .u64 t; cvta.to.shared.u64 t, %1; cvt.u32.u64 %0, t; }"
        : "=r"(a) : "l"(p));
    return a;
}

// pack two f32 -> bf16x2 reg, v0 in low half (memory element 0)
#define PACK_BF16X2(res, v0, v1) \
    asm("cvt.rn.bf16x2.f32 %0, %1, %2;" : "=r"(res) : "f"(v1), "f"(v0))

#define LDM_X4(r, addr) \
    asm volatile("ldmatrix.sync.aligned.m8n8.x4.shared.b16 {%0,%1,%2,%3}, [%4];" \
        : "=r"((r)[0]), "=r"((r)[1]), "=r"((r)[2]), "=r"((r)[3]) : "r"(addr))

#define MMA16816(d, a, bp) \
    asm volatile("mma.sync.aligned.m16n8k16.row.col.f32.bf16.bf16.f32 " \
        "{%0,%1,%2,%3}, {%4,%5,%6,%7}, {%8,%9}, {%0,%1,%2,%3};" \
        : "+f"((d)[0]), "+f"((d)[1]), "+f"((d)[2]), "+f"((d)[3]) \
        : "r"((a)[0]), "r"((a)[1]), "r"((a)[2]), "r"((a)[3]), \
          "r"((bp)[0]), "r"((bp)[1]))

// smem tile: 128 rows x 128 bf16, row stride 272B (17*16 -> conflict-free)
#define TROW 272
#define TILE (128 * TROW)
#define GEMM_SMEM (4 * TILE)   // 139264

// ---------------------------------------------------------------------------
// Kernel A: split x (f32 [b][c][p]) -> g_xhi/g_xlo (bf16 [b][p][c])
// ---------------------------------------------------------------------------
__global__ __launch_bounds__(256) void xsplit_kernel(const float* __restrict__ x)
{
    __shared__ float t[32][33];
    const int p0 = blockIdx.x * 32, c0 = blockIdx.y * 32, b = blockIdx.z;
    const int tl = threadIdx.x & 31, th = threadIdx.x >> 5;
#pragma unroll
    for (int i = 0; i < 4; i++) {
        int c = th + i * 8;
        t[c][tl] = x[((size_t)b * C + c0 + c) * HW + p0 + tl];
    }
    __syncthreads();
#pragma unroll
    for (int i = 0; i < 4; i++) {
        int p = th + i * 8;
        float v = t[tl][p];
        __nv_bfloat16 hb = __float2bfloat16(v);
        float lov = v - __bfloat162float(hb);
        size_t off = ((size_t)b * HW + p0 + p) * C + c0 + tl;
        g_xhi[off] = hb;
        g_xlo[off] = __float2bfloat16(lov);
    }
}

// ---------------------------------------------------------------------------
// Kernel B: bake weights -> bf16 hi/lo [mat][o][c]
// ---------------------------------------------------------------------------
__global__ __launch_bounds__(256) void wbake_kernel(
    const float* __restrict__ wq, const float* __restrict__ wk,
    const float* __restrict__ wv, const float* __restrict__ wp)
{
    const int mat = blockIdx.y;
    const float* __restrict__ src =
        (mat == 0) ? wq : (mat == 1) ? wk : (mat == 2) ? wv : wp;
    int idx = blockIdx.x * 256 + threadIdx.x;
    float w = src[idx];
    __nv_bfloat16 hb = __float2bfloat16(w);
    float lov = w - __bfloat162float(hb);
    g_whi[mat * 16384 + idx] = hb;
    g_wlo[mat * 16384 + idx] = __float2bfloat16(lov);
}

// ---------------------------------------------------------------------------
// Shared HMMA mainloop (validated in R5)
// ---------------------------------------------------------------------------
__device__ __forceinline__ void mma_tiles(
    uint32_t Abase, uint32_t Bbase, int lane, int mwarp, int nwarp,
    float (*acc)[4])
{
    const uint32_t arow0 = Abase + (uint32_t)(mwarp + (lane & 15)) * TROW
                         + ((lane >> 4) & 1) * 16;
    const uint32_t brow0 = Bbase
                         + (uint32_t)(nwarp + ((lane >> 4) << 3) + (lane & 7)) * TROW
                         + ((lane >> 3) & 1) * 16;
#pragma unroll
    for (int k0 = 0; k0 < 8; k0++) {
        uint32_t a[4][4], bq[2][4];
#pragma unroll
        for (int mt = 0; mt < 4; mt++)
            LDM_X4(a[mt], arow0 + k0 * 32 + mt * (16 * TROW));
#pragma unroll
        for (int n2 = 0; n2 < 2; n2++)
            LDM_X4(bq[n2], brow0 + k0 * 32 + n2 * (16 * TROW));
#pragma unroll
        for (int mt = 0; mt < 4; mt++)
#pragma unroll
            for (int nt = 0; nt < 4; nt++)
                MMA16816(acc[mt * 4 + nt], a[mt], &bq[nt >> 1][(nt & 1) * 2]);
    }
}

__device__ __forceinline__ void stage_tile(
    uint32_t dst, const __nv_bfloat16* __restrict__ src, int tid)
{
    for (int i = tid; i < 2048; i += 256) {
        int r = i >> 4, ch = i & 15;
        cp16(dst + r * TROW + ch * 16, src + r * 128 + ch * 8);
    }
}

// ---------------------------------------------------------------------------
// Kernel 1: QKV. A = X (pixels) hi/lo, B = W hi/lo. D[p][o].
// ---------------------------------------------------------------------------
__global__ __launch_bounds__(256) void qkv_mma_kernel()
{
    extern __shared__ char sm[];
    const uint32_t smb = smem_u32(sm);
    const int tid = threadIdx.x, wid = tid >> 5, lane = tid & 31;
    const int pb = blockIdx.x, mat = blockIdx.y, b = blockIdx.z;
    const int p0 = pb * 128;

    const __nv_bfloat16* xh = g_xhi + ((size_t)b * HW + p0) * C;
    const __nv_bfloat16* xl = g_xlo + ((size_t)b * HW + p0) * C;
    const __nv_bfloat16* wh = g_whi + mat * 16384;
    const __nv_bfloat16* wl = g_wlo + mat * 16384;

    stage_tile(smb + 0 * TILE, xh, tid);
    stage_tile(smb + 2 * TILE, wh, tid);
    CP_COMMIT();
    stage_tile(smb + 1 * TILE, xl, tid);
    stage_tile(smb + 3 * TILE, wl, tid);
    CP_COMMIT();

    float acc[16][4];
#pragma unroll
    for (int i = 0; i < 16; i++)
#pragma unroll
        for (int j = 0; j < 4; j++) acc[i][j] = 0.f;

    const int mwarp = (wid >> 2) * 64, nwarp = (wid & 3) * 32;

    CP_WAIT(1);
    __syncthreads();
    mma_tiles(smb + 0 * TILE, smb + 2 * TILE, lane, mwarp, nwarp, acc);
    CP_WAIT(0);
    __syncthreads();
    mma_tiles(smb + 0 * TILE, smb + 3 * TILE, lane, mwarp, nwarp, acc);
    mma_tiles(smb + 1 * TILE, smb + 2 * TILE, lane, mwarp, nwarp, acc);

    const int gid = lane >> 2, tig = lane & 3;
#pragma unroll
    for (int mt = 0; mt < 4; mt++) {
#pragma unroll
        for (int half = 0; half < 2; half++) {
            int r = mwarp + mt * 16 + gid + half * 8;
            int p = p0 + r;
            float* dst;
            if (mat == 0) {
                dst = g_q + ((size_t)b * HW + p) * INNER;
            } else {
                int yy = p / W, xx = p - yy * W;
                float* base = (mat == 1) ? g_kpad : g_vpad;
                dst = base + (((size_t)b * HP + yy + PAD) * WP + (xx + PAD)) * INNER;
            }
#pragma unroll
            for (int nt = 0; nt < 4; nt++) {
                int o = nwarp + nt * 8 + 2 * tig;
                *(float2*)(dst + o) = make_float2(acc[mt * 4 + nt][half * 2],
                                                  acc[mt * 4 + nt][half * 2 + 1]);
            }
        }
    }
}

// ---------------------------------------------------------------------------
// Kernel 2: window attention, fused one-pass (no score arrays, no max-sub).
// Thread = (pixel pair along x, d-half): 2 pixels x 16 channels.
// Per tap: load k AND v (8 independent LDS.128), dot, shfl-join halves,
// e = expf(s*scale), o += e*v, sum += e. Final: out = o / sum.
// Scores ~N(0,1) so exp without max-subtraction is safe in fp32, and padded
// taps contribute exp(0)=1 exactly as in the reference.
// ---------------------------------------------------------------------------
#define TX 32
#define TY 8
#define PWT (TX + 4)     // 36
#define PHT (TY + 4)     // 12
#define NPIX (PWT * PHT) // 432
#define DGS 433
#define ATTN_SMEM (2 * 8 * DGS * 16)   // 110848

__global__ __launch_bounds__(256, 2) void attn_kernel()
{
    extern __shared__ float4 sm4[];
    float4* ks4 = sm4;
    float4* vs4 = sm4 + 8 * DGS;
    const uint32_t smbk = smem_u32(ks4);
    const uint32_t smbv = smem_u32(vs4);

    const int t  = threadIdx.x;
    const int x0 = blockIdx.x * TX;
    const int y0 = blockIdx.y * TY;
    const int h  = blockIdx.z & 3;
    const int b  = blockIdx.z >> 2;

    const float* __restrict__ kg =
        g_kpad + (((size_t)b * HP + y0) * WP + x0) * INNER + h * DHEAD;
    const float* __restrict__ vg =
        g_vpad + (((size_t)b * HP + y0) * WP + x0) * INNER + h * DHEAD;

    // fill halo: pixel pp, channel group g (g = hh*4 + dgl) -> plane dgl*2+hh
#pragma unroll
    for (int i = t; i < NPIX * 8; i += 256) {
        int pp = i >> 3, g = i & 7;
        int py = pp / PWT, px = pp - py * PWT;
        int pl = ((g & 3) << 1) | (g >> 2);
        size_t goff = ((size_t)py * WP + px) * INNER + g * 4;
        cp16(smbk + (uint32_t)(pl * DGS + pp) * 16, kg + goff);
        cp16(smbv + (uint32_t)(pl * DGS + pp) * 16, vg + goff);
    }
    CP_COMMIT();

    const int hh   = t & 1;          // d-half
    const int pair = t >> 1;         // 0..127
    const int tx2  = pair & 15;      // pair column (pixels 2*tx2, 2*tx2+1)
    const int ty   = pair >> 4;      // 0..7
    const int p0p  = (y0 + ty) * W + x0 + 2 * tx2;

    // q (pre-scaled) for both pixels, this d-half
    const float scale = 0.17677669529663687f;  // 1/sqrt(32)
    float q0f[16], q1f[16];
    {
        const float* qp0 = g_q + ((size_t)b * HW + p0p) * INNER + h * DHEAD + hh * 16;
        const float* qp1 = qp0 + INNER;
#pragma unroll
        for (int i = 0; i < 4; i++) {
            float4 v0 = *(const float4*)(qp0 + i * 4);
            float4 v1 = *(const float4*)(qp1 + i * 4);
            q0f[4 * i] = v0.x * scale; q0f[4 * i + 1] = v0.y * scale;
            q0f[4 * i + 2] = v0.z * scale; q0f[4 * i + 3] = v0.w * scale;
            q1f[4 * i] = v1.x * scale; q1f[4 * i + 1] = v1.y * scale;
            q1f[4 * i + 2] = v1.z * scale; q1f[4 * i + 3] = v1.w * scale;
        }
    }
    u64 q0[8], q1[8];
#pragma unroll
    for (int i = 0; i < 8; i++) {
        q0[i] = *(u64*)&q0f[2 * i];
        q1[i] = *(u64*)&q1f[2 * i];
    }

    CP_WAIT(0);
    __syncthreads();

    u64 o0[8], o1[8];
#pragma unroll
    for (int i = 0; i < 8; i++) { o0[i] = 0ull; o1[i] = 0ull; }
    float sum0 = 0.f, sum1 = 0.f;

#pragma unroll
    for (int di = 0; di < 5; di++) {
#pragma unroll
        for (int djj = 0; djj < 6; djj++) {
            const int pixi = (ty + di) * PWT + 2 * tx2 + djj;
            // load k and v for this tap (8 independent LDS.128)
            u64 kk[8], vv[8];
#pragma unroll
            for (int dgl = 0; dgl < 4; dgl++) {
                ulonglong2 kq = *(const ulonglong2*)&ks4[(dgl * 2 + hh) * DGS + pixi];
                ulonglong2 vq = *(const ulonglong2*)&vs4[(dgl * 2 + hh) * DGS + pixi];
                kk[2 * dgl] = kq.x; kk[2 * dgl + 1] = kq.y;
                vv[2 * dgl] = vq.x; vv[2 * dgl + 1] = vq.y;
            }
            // partial dots (both pixels; q pre-scaled)
            u64 a0 = 0ull, a1 = 0ull, b0 = 0ull, b1 = 0ull;
#pragma unroll
            for (int j = 0; j < 4; j++) {
                FFMA2(a0, q0[2 * j], kk[2 * j]);
                FFMA2(a1, q0[2 * j + 1], kk[2 * j + 1]);
                FFMA2(b0, q1[2 * j], kk[2 * j]);
                FFMA2(b1, q1[2 * j + 1], kk[2 * j + 1]);
            }
            float2 fa0 = *(float2*)&a0, fa1 = *(float2*)&a1;
            float2 fb0 = *(float2*)&b0, fb1 = *(float2*)&b1;
            float p0s = (fa0.x + fa0.y) + (fa1.x + fa1.y);
            float p1s = (fb0.x + fb0.y) + (fb1.x + fb1.y);
            // join d-halves
            p0s += __shfl_xor_sync(0xffffffffu, p0s, 1);
            p1s += __shfl_xor_sync(0xffffffffu, p1s, 1);
            if (djj < 5) {
                float e = __expf(p0s);
                sum0 += e;
                u64 w2;
                PACK2(w2, e);
#pragma unroll
                for (int j = 0; j < 8; j++) FFMA2(o0[j], w2, vv[j]);
            }
            if (djj > 0) {
                float e = __expf(p1s);
                sum1 += e;
                u64 w2;
                PACK2(w2, e);
#pragma unroll
                for (int j = 0; j < 8; j++) FFMA2(o1[j], w2, vv[j]);
            }
        }
    }

    const float inv0 = 1.f / sum0, inv1 = 1.f / sum1;

    // split to bf16 hi/lo and store both pixels' 16-channel halves
#pragma unroll
    for (int px = 0; px < 2; px++) {
        const u64* oo = px ? o1 : o0;
        const float inv = px ? inv1 : inv0;
        uint32_t hu[8], lu[8];
#pragma unroll
        for (int i = 0; i < 8; i++) {
            float2 f = *(float2*)&oo[i];
            float a = f.x * inv, bb = f.y * inv;
            __nv_bfloat16 ha = __float2bfloat16(a), hb = __float2bfloat16(bb);
            float la = a - __bfloat162float(ha);
            float lb = bb - __bfloat162float(hb);
            PACK_BF16X2(hu[i], a, bb);
            PACK_BF16X2(lu[i], la, lb);
        }
        __nv_bfloat16* oh = g_ohi + ((size_t)b * HW + p0p + px) * INNER + h * DHEAD + hh * 16;
        __nv_bfloat16* ol = g_olo + ((size_t)b * HW + p0p + px) * INNER + h * DHEAD + hh * 16;
#pragma unroll
        for (int cc = 0; cc < 2; cc++) {
            *(uint4*)(oh + cc * 8) = make_uint4(hu[4 * cc], hu[4 * cc + 1],
                                                hu[4 * cc + 2], hu[4 * cc + 3]);
            *(uint4*)(ol + cc * 8) = make_uint4(lu[4 * cc], lu[4 * cc + 1],
                                                lu[4 * cc + 2], lu[4 * cc + 3]);
        }
    }
}

// ---------------------------------------------------------------------------
// Kernel 3: proj. A = wproj hi/lo, B = attn-out hi/lo. D[c][p] -> NCHW.
// ---------------------------------------------------------------------------
__global__ __launch_bounds__(256) void proj_mma_kernel(float* __restrict__ outp)
{
    extern __shared__ char sm[];
    const uint32_t smb = smem_u32(sm);
    const int tid = threadIdx.x, wid = tid >> 5, lane = tid & 31;
    const int pb = blockIdx.x, b = blockIdx.y;
    const int p0 = pb * 128;

    const __nv_bfloat16* ah = g_whi + 3 * 16384;
    const __nv_bfloat16* al = g_wlo + 3 * 16384;
    const __nv_bfloat16* bh = g_ohi + ((size_t)b * HW + p0) * INNER;
    const __nv_bfloat16* bl = g_olo + ((size_t)b * HW + p0) * INNER;

    stage_tile(smb + 0 * TILE, ah, tid);
    stage_tile(smb + 2 * TILE, bh, tid);
    CP_COMMIT();
    stage_tile(smb + 1 * TILE, al, tid);
    stage_tile(smb + 3 * TILE, bl, tid);
    CP_COMMIT();

    float acc[16][4];
#pragma unroll
    for (int i = 0; i < 16; i++)
#pragma unroll
        for (int j = 0; j < 4; j++) acc[i][j] = 0.f;

    const int mwarp = (wid >> 2) * 64, nwarp = (wid & 3) * 32;

    CP_WAIT(1);
    __syncthreads();
    mma_tiles(smb + 0 * TILE, smb + 2 * TILE, lane, mwarp, nwarp, acc);
    CP_WAIT(0);
    __syncthreads();
    mma_tiles(smb + 0 * TILE, smb + 3 * TILE, lane, mwarp, nwarp, acc);
    mma_tiles(smb + 1 * TILE, smb + 2 * TILE, lane, mwarp, nwarp, acc);

    const int gid = lane >> 2, tig = lane & 3;
#pragma unroll
    for (int mt = 0; mt < 4; mt++) {
#pragma unroll
        for (int half = 0; half < 2; half++) {
            int c = mwarp + mt * 16 + gid + half * 8;
            float* dst = outp + ((size_t)b * C + c) * HW + p0;
#pragma unroll
            for (int nt = 0; nt < 4; nt++) {
                int col = nwarp + nt * 8 + 2 * tig;
                *(float2*)(dst + col) = make_float2(acc[mt * 4 + nt][half * 2],
                                                    acc[mt * 4 + nt][half * 2 + 1]);
            }
        }
    }
}

extern "C" void kernel_launch(void* const* d_in, const int* in_sizes, int n_in,
                              void* d_out, int out_size)
{
    const float* x     = (const float*)d_in[0];
    const float* wq    = (const float*)d_in[1];
    const float* wk    = (const float*)d_in[2];
    const float* wv    = (const float*)d_in[3];
    const float* wproj = (const float*)d_in[4];
    float* outp = (float*)d_out;

    cudaFuncSetAttribute(attn_kernel,
                         cudaFuncAttributeMaxDynamicSharedMemorySize, ATTN_SMEM);
    cudaFuncSetAttribute(qkv_mma_kernel,
                         cudaFuncAttributeMaxDynamicSharedMemorySize, GEMM_SMEM);
    cudaFuncSetAttribute(proj_mma_kernel,
                         cudaFuncAttributeMaxDynamicSharedMemorySize, GEMM_SMEM);

    wbake_kernel<<<dim3(64, 4), 256>>>(wq, wk, wv, wproj);
    xsplit_kernel<<<dim3(HW / 32, C / 32, BATCH), 256>>>(x);
    qkv_mma_kernel<<<dim3(NTILES, 3, BATCH), 256, GEMM_SMEM>>>();
    attn_kernel<<<dim3(W / TX, H / TY, HEADS * BATCH), 256, ATTN_SMEM>>>();
    proj_mma_kernel<<<dim3(NTILES, BATCH), 256, GEMM_SMEM>>>(outp);
}

// round 10
// speedup vs baseline: 1.0061x; 1.0061x over previous
#include <cuda_runtime.h>
#include <cuda_bf16.h>
#include <cstdint>

#define BATCH 2
#define C 128
#define H 96
#define W 96
#define HEADS 4
#define DHEAD 32
#define PAD 2
#define INNER 128
#define HW (H * W)
#define HP (H + 2 * PAD)
#define WP (W + 2 * PAD)
#define NTILES (HW / 128)   // 72

typedef unsigned long long u64;

// fp32 scratch
__device__ float g_q[(size_t)BATCH * HW * INNER];          // [b][p][inner]
__device__ float g_kpad[(size_t)BATCH * HP * WP * INNER];  // [b][yp][xp][inner]
__device__ float g_vpad[(size_t)BATCH * HP * WP * INNER];

// bf16 hi/lo operand images
__device__ __nv_bfloat16 g_xhi[(size_t)BATCH * HW * C];    // [b][p][c]
__device__ __nv_bfloat16 g_xlo[(size_t)BATCH * HW * C];
__device__ __nv_bfloat16 g_whi[4 * C * INNER];             // [mat][o][c]
__device__ __nv_bfloat16 g_wlo[4 * C * INNER];
__device__ __nv_bfloat16 g_ohi[(size_t)BATCH * HW * INNER];// [b][p][inner]
__device__ __nv_bfloat16 g_olo[(size_t)BATCH * HW * INNER];

#define FFMA2(d, a, b) \
    asm("fma.rn.f32x2 %0, %1, %2, %0;" : "+l"(d) : "l"(a), "l"(b))
#define PACK2(d, s) \
    asm("mov.b64 %0, {%1, %1};" : "=l"(d) : "f"(s))

__device__ __forceinline__ void cp16(uint32_t smem, const void* g) {
    asm volatile("cp.async.cg.shared.global [%0], [%1], 16;" :: "r"(smem), "l"(g));
}
#define CP_COMMIT() asm volatile("cp.async.commit_group;")
#define CP_WAIT(n)  asm volatile("cp.async.wait_group %0;" :: "n"(n))

__device__ __forceinline__ uint32_t smem_u32(const void* p) {
    uint32_t a;
    asm("{ .reg .u64 t; cvta.to.shared.u64 t, %1; cvt.u32.u64 %0, t; }"
        : "=r"(a) : "l"(p));
    return a;
}

// pack two f32 -> bf16x2 reg, v0 in low half (memory element 0)
#define PACK_BF16X2(res, v0, v1) \
    asm("cvt.rn.bf16x2.f32 %0, %1, %2;" : "=r"(res) : "f"(v1), "f"(v0))

#define LDM_X4(r, addr) \
    asm volatile("ldmatrix.sync.aligned.m8n8.x4.shared.b16 {%0,%1,%2,%3}, [%4];" \
        : "=r"((r)[0]), "=r"((r)[1]), "=r"((r)[2]), "=r"((r)[3]) : "r"(addr))

#define MMA16816(d, a, bp) \
    asm volatile("mma.sync.aligned.m16n8k16.row.col.f32.bf16.bf16.f32 " \
        "{%0,%1,%2,%3}, {%4,%5,%6,%7}, {%8,%9}, {%0,%1,%2,%3};" \
        : "+f"((d)[0]), "+f"((d)[1]), "+f"((d)[2]), "+f"((d)[3]) \
        : "r"((a)[0]), "r"((a)[1]), "r"((a)[2]), "r"((a)[3]), \
          "r"((bp)[0]), "r"((bp)[1]))

// smem tile: 128 rows x 128 bf16, row stride 272B (17*16 -> conflict-free)
#define TROW 272
#define TILE (128 * TROW)
#define GEMM_SMEM (3 * TILE)   // 104448 -> 2 blocks/SM

// ---------------------------------------------------------------------------
// Kernel A: split x (f32 [b][c][p]) -> g_xhi/g_xlo (bf16 [b][p][c])
// ---------------------------------------------------------------------------
__global__ __launch_bounds__(256) void xsplit_kernel(const float* __restrict__ x)
{
    __shared__ float t[32][33];
    const int p0 = blockIdx.x * 32, c0 = blockIdx.y * 32, b = blockIdx.z;
    const int tl = threadIdx.x & 31, th = threadIdx.x >> 5;
#pragma unroll
    for (int i = 0; i < 4; i++) {
        int c = th + i * 8;
        t[c][tl] = x[((size_t)b * C + c0 + c) * HW + p0 + tl];
    }
    __syncthreads();
#pragma unroll
    for (int i = 0; i < 4; i++) {
        int p = th + i * 8;
        float v = t[tl][p];
        __nv_bfloat16 hb = __float2bfloat16(v);
        float lov = v - __bfloat162float(hb);
        size_t off = ((size_t)b * HW + p0 + p) * C + c0 + tl;
        g_xhi[off] = hb;
        g_xlo[off] = __float2bfloat16(lov);
    }
}

// ---------------------------------------------------------------------------
// Kernel B: bake weights -> bf16 hi/lo [mat][o][c]
// ---------------------------------------------------------------------------
__global__ __launch_bounds__(256) void wbake_kernel(
    const float* __restrict__ wq, const float* __restrict__ wk,
    const float* __restrict__ wv, const float* __restrict__ wp)
{
    const int mat = blockIdx.y;
    const float* __restrict__ src =
        (mat == 0) ? wq : (mat == 1) ? wk : (mat == 2) ? wv : wp;
    int idx = blockIdx.x * 256 + threadIdx.x;
    float w = src[idx];
    __nv_bfloat16 hb = __float2bfloat16(w);
    float lov = w - __bfloat162float(hb);
    g_whi[mat * 16384 + idx] = hb;
    g_wlo[mat * 16384 + idx] = __float2bfloat16(lov);
}

// ---------------------------------------------------------------------------
// Shared HMMA mainloop (validated in R5)
// ---------------------------------------------------------------------------
__device__ __forceinline__ void mma_tiles(
    uint32_t Abase, uint32_t Bbase, int lane, int mwarp, int nwarp,
    float (*acc)[4])
{
    const uint32_t arow0 = Abase + (uint32_t)(mwarp + (lane & 15)) * TROW
                         + ((lane >> 4) & 1) * 16;
    const uint32_t brow0 = Bbase
                         + (uint32_t)(nwarp + ((lane >> 4) << 3) + (lane & 7)) * TROW
                         + ((lane >> 3) & 1) * 16;
#pragma unroll
    for (int k0 = 0; k0 < 8; k0++) {
        uint32_t a[4][4], bq[2][4];
#pragma unroll
        for (int mt = 0; mt < 4; mt++)
            LDM_X4(a[mt], arow0 + k0 * 32 + mt * (16 * TROW));
#pragma unroll
        for (int n2 = 0; n2 < 2; n2++)
            LDM_X4(bq[n2], brow0 + k0 * 32 + n2 * (16 * TROW));
#pragma unroll
        for (int mt = 0; mt < 4; mt++)
#pragma unroll
            for (int nt = 0; nt < 4; nt++)
                MMA16816(acc[mt * 4 + nt], a[mt], &bq[nt >> 1][(nt & 1) * 2]);
    }
}

__device__ __forceinline__ void stage_tile(
    uint32_t dst, const __nv_bfloat16* __restrict__ src, int tid)
{
    for (int i = tid; i < 2048; i += 256) {
        int r = i >> 4, ch = i & 15;
        cp16(dst + r * TROW + ch * 16, src + r * 128 + ch * 8);
    }
}

// 3-pass GEMM core with 3 smem buffers (Ahi, Bhi persistent; swap = Blo->Alo)
__device__ __forceinline__ void gemm3(
    uint32_t smb,
    const __nv_bfloat16* __restrict__ ah, const __nv_bfloat16* __restrict__ al,
    const __nv_bfloat16* __restrict__ bh, const __nv_bfloat16* __restrict__ bl,
    int tid, int lane, int mwarp, int nwarp, float (*acc)[4])
{
    const uint32_t AHI = smb, BHI = smb + TILE, SWP = smb + 2 * TILE;

    stage_tile(AHI, ah, tid);
    stage_tile(BHI, bh, tid);
    CP_COMMIT();
    stage_tile(SWP, bl, tid);
    CP_COMMIT();

    CP_WAIT(1);
    __syncthreads();
    mma_tiles(AHI, BHI, lane, mwarp, nwarp, acc);   // hi*hi
    CP_WAIT(0);
    __syncthreads();
    mma_tiles(AHI, SWP, lane, mwarp, nwarp, acc);   // hi*lo
    __syncthreads();                                 // SWP reads done
    stage_tile(SWP, al, tid);
    CP_COMMIT();
    CP_WAIT(0);
    __syncthreads();
    mma_tiles(SWP, BHI, lane, mwarp, nwarp, acc);   // lo*hi
}

// ---------------------------------------------------------------------------
// Kernel 1: QKV. A = X (pixels) hi/lo, B = W hi/lo. D[p][o].
// ---------------------------------------------------------------------------
__global__ __launch_bounds__(256) void qkv_mma_kernel()
{
    extern __shared__ char sm[];
    const uint32_t smb = smem_u32(sm);
    const int tid = threadIdx.x, wid = tid >> 5, lane = tid & 31;
    const int pb = blockIdx.x, mat = blockIdx.y, b = blockIdx.z;
    const int p0 = pb * 128;

    float acc[16][4];
#pragma unroll
    for (int i = 0; i < 16; i++)
#pragma unroll
        for (int j = 0; j < 4; j++) acc[i][j] = 0.f;

    const int mwarp = (wid >> 2) * 64, nwarp = (wid & 3) * 32;

    gemm3(smb,
          g_xhi + ((size_t)b * HW + p0) * C, g_xlo + ((size_t)b * HW + p0) * C,
          g_whi + mat * 16384, g_wlo + mat * 16384,
          tid, lane, mwarp, nwarp, acc);

    const int gid = lane >> 2, tig = lane & 3;
#pragma unroll
    for (int mt = 0; mt < 4; mt++) {
#pragma unroll
        for (int half = 0; half < 2; half++) {
            int r = mwarp + mt * 16 + gid + half * 8;
            int p = p0 + r;
            float* dst;
            if (mat == 0) {
                dst = g_q + ((size_t)b * HW + p) * INNER;
            } else {
                int yy = p / W, xx = p - yy * W;
                float* base = (mat == 1) ? g_kpad : g_vpad;
                dst = base + (((size_t)b * HP + yy + PAD) * WP + (xx + PAD)) * INNER;
            }
#pragma unroll
            for (int nt = 0; nt < 4; nt++) {
                int o = nwarp + nt * 8 + 2 * tig;
                *(float2*)(dst + o) = make_float2(acc[mt * 4 + nt][half * 2],
                                                  acc[mt * 4 + nt][half * 2 + 1]);
            }
        }
    }
}

// ---------------------------------------------------------------------------
// Kernel 2: window attention, pixel-pair + d-split, two-phase (R8, best).
// ---------------------------------------------------------------------------
#define TX 32
#define TY 8
#define PWT (TX + 4)     // 36
#define PHT (TY + 4)     // 12
#define NPIX (PWT * PHT) // 432
#define DGS 433
#define ATTN_SMEM (2 * 8 * DGS * 16)   // 110848

__global__ __launch_bounds__(256, 2) void attn_kernel()
{
    extern __shared__ float4 sm4[];
    float4* ks4 = sm4;
    float4* vs4 = sm4 + 8 * DGS;
    const uint32_t smbk = smem_u32(ks4);
    const uint32_t smbv = smem_u32(vs4);

    const int t  = threadIdx.x;
    const int x0 = blockIdx.x * TX;
    const int y0 = blockIdx.y * TY;
    const int h  = blockIdx.z & 3;
    const int b  = blockIdx.z >> 2;

    const float* __restrict__ kg =
        g_kpad + (((size_t)b * HP + y0) * WP + x0) * INNER + h * DHEAD;
    const float* __restrict__ vg =
        g_vpad + (((size_t)b * HP + y0) * WP + x0) * INNER + h * DHEAD;

    // fill halo: pixel pp, channel group g (g = hh*4 + dgl) -> plane dgl*2+hh
#pragma unroll
    for (int i = t; i < NPIX * 8; i += 256) {
        int pp = i >> 3, g = i & 7;
        int py = pp / PWT, px = pp - py * PWT;
        int pl = ((g & 3) << 1) | (g >> 2);
        size_t goff = ((size_t)py * WP + px) * INNER + g * 4;
        cp16(smbk + (uint32_t)(pl * DGS + pp) * 16, kg + goff);
        cp16(smbv + (uint32_t)(pl * DGS + pp) * 16, vg + goff);
    }
    CP_COMMIT();

    const int hh   = t & 1;          // d-half
    const int pair = t >> 1;         // 0..127
    const int tx2  = pair & 15;      // pair column (pixels 2*tx2, 2*tx2+1)
    const int ty   = pair >> 4;      // 0..7
    const int p0p  = (y0 + ty) * W + x0 + 2 * tx2;

    // q for both pixels, this d-half (16 channels each)
    u64 q0[8], q1[8];
    {
        const float* qp0 = g_q + ((size_t)b * HW + p0p) * INNER + h * DHEAD + hh * 16;
        const float* qp1 = qp0 + INNER;
#pragma unroll
        for (int i = 0; i < 4; i++) {
            ulonglong2 v0 = *(const ulonglong2*)(qp0 + i * 4);
            ulonglong2 v1 = *(const ulonglong2*)(qp1 + i * 4);
            q0[2 * i] = v0.x; q0[2 * i + 1] = v0.y;
            q1[2 * i] = v1.x; q1[2 * i + 1] = v1.y;
        }
    }

    CP_WAIT(0);
    __syncthreads();

    // score partials (this half): 25 per pixel
    float s0[25], s1[25];
#pragma unroll
    for (int di = 0; di < 5; di++) {
#pragma unroll
        for (int djj = 0; djj < 6; djj++) {
            const int pixi = (ty + di) * PWT + 2 * tx2 + djj;
            u64 kk[8];
#pragma unroll
            for (int dgl = 0; dgl < 4; dgl++) {
                ulonglong2 kv = *(const ulonglong2*)&ks4[(dgl * 2 + hh) * DGS + pixi];
                kk[2 * dgl] = kv.x; kk[2 * dgl + 1] = kv.y;
            }
            if (djj < 5) {
                u64 a0 = 0ull, a1 = 0ull;
#pragma unroll
                for (int j = 0; j < 4; j++) {
                    FFMA2(a0, q0[2 * j], kk[2 * j]);
                    FFMA2(a1, q0[2 * j + 1], kk[2 * j + 1]);
                }
                float2 fa = *(float2*)&a0, fb = *(float2*)&a1;
                s0[di * 5 + djj] = (fa.x + fa.y) + (fb.x + fb.y);
            }
            if (djj > 0) {
                u64 a0 = 0ull, a1 = 0ull;
#pragma unroll
                for (int j = 0; j < 4; j++) {
                    FFMA2(a0, q1[2 * j], kk[2 * j]);
                    FFMA2(a1, q1[2 * j + 1], kk[2 * j + 1]);
                }
                float2 fa = *(float2*)&a0, fb = *(float2*)&a1;
                s1[di * 5 + djj - 1] = (fa.x + fa.y) + (fb.x + fb.y);
            }
        }
    }

    // join d-halves
    const float scale = 0.17677669529663687f;  // 1/sqrt(32)
#pragma unroll
    for (int n = 0; n < 25; n++) {
        s0[n] = (s0[n] + __shfl_xor_sync(0xffffffffu, s0[n], 1)) * scale;
        s1[n] = (s1[n] + __shfl_xor_sync(0xffffffffu, s1[n], 1)) * scale;
    }

    // softmax (both pixels; duplicated across halves)
    float m0 = s0[0], m1 = s1[0];
#pragma unroll
    for (int n = 1; n < 25; n++) {
        m0 = fmaxf(m0, s0[n]);
        m1 = fmaxf(m1, s1[n]);
    }
    float sum0 = 0.f, sum1 = 0.f;
#pragma unroll
    for (int n = 0; n < 25; n++) {
        float e0 = __expf(s0[n] - m0);
        float e1 = __expf(s1[n] - m1);
        s0[n] = e0; s1[n] = e1;
        sum0 += e0; sum1 += e1;
    }
    const float inv0 = 1.f / sum0, inv1 = 1.f / sum1;

    // AV: this half's 16 channels for both pixels
    u64 o0[8], o1[8];
#pragma unroll
    for (int i = 0; i < 8; i++) { o0[i] = 0ull; o1[i] = 0ull; }
#pragma unroll
    for (int di = 0; di < 5; di++) {
#pragma unroll
        for (int djj = 0; djj < 6; djj++) {
            const int pixi = (ty + di) * PWT + 2 * tx2 + djj;
            u64 vv[8];
#pragma unroll
            for (int dgl = 0; dgl < 4; dgl++) {
                ulonglong2 vq = *(const ulonglong2*)&vs4[(dgl * 2 + hh) * DGS + pixi];
                vv[2 * dgl] = vq.x; vv[2 * dgl + 1] = vq.y;
            }
            if (djj < 5) {
                u64 w2;
                PACK2(w2, s0[di * 5 + djj]);
#pragma unroll
                for (int j = 0; j < 8; j++) FFMA2(o0[j], w2, vv[j]);
            }
            if (djj > 0) {
                u64 w2;
                PACK2(w2, s1[di * 5 + djj - 1]);
#pragma unroll
                for (int j = 0; j < 8; j++) FFMA2(o1[j], w2, vv[j]);
            }
        }
    }

    // split to bf16 hi/lo and store both pixels' 16-channel halves
#pragma unroll
    for (int px = 0; px < 2; px++) {
        const u64* oo = px ? o1 : o0;
        const float inv = px ? inv1 : inv0;
        uint32_t hu[8], lu[8];
#pragma unroll
        for (int i = 0; i < 8; i++) {
            float2 f = *(float2*)&oo[i];
            float a = f.x * inv, bb = f.y * inv;
            __nv_bfloat16 ha = __float2bfloat16(a), hb = __float2bfloat16(bb);
            float la = a - __bfloat162float(ha);
            float lb = bb - __bfloat162float(hb);
            PACK_BF16X2(hu[i], a, bb);
            PACK_BF16X2(lu[i], la, lb);
        }
        __nv_bfloat16* oh = g_ohi + ((size_t)b * HW + p0p + px) * INNER + h * DHEAD + hh * 16;
        __nv_bfloat16* ol = g_olo + ((size_t)b * HW + p0p + px) * INNER + h * DHEAD + hh * 16;
#pragma unroll
        for (int cc = 0; cc < 2; cc++) {
            *(uint4*)(oh + cc * 8) = make_uint4(hu[4 * cc], hu[4 * cc + 1],
                                                hu[4 * cc + 2], hu[4 * cc + 3]);
            *(uint4*)(ol + cc * 8) = make_uint4(lu[4 * cc], lu[4 * cc + 1],
                                                lu[4 * cc + 2], lu[4 * cc + 3]);
        }
    }
}

// ---------------------------------------------------------------------------
// Kernel 3: proj. A = wproj hi/lo, B = attn-out hi/lo. D[c][p] -> NCHW.
// ---------------------------------------------------------------------------
__global__ __launch_bounds__(256) void proj_mma_kernel(float* __restrict__ outp)
{
    extern __shared__ char sm[];
    const uint32_t smb = smem_u32(sm);
    const int tid = threadIdx.x, wid = tid >> 5, lane = tid & 31;
    const int pb = blockIdx.x, b = blockIdx.y;
    const int p0 = pb * 128;

    float acc[16][4];
#pragma unroll
    for (int i = 0; i < 16; i++)
#pragma unroll
        for (int j = 0; j < 4; j++) acc[i][j] = 0.f;

    const int mwarp = (wid >> 2) * 64, nwarp = (wid & 3) * 32;

    gemm3(smb,
          g_whi + 3 * 16384, g_wlo + 3 * 16384,
          g_ohi + ((size_t)b * HW + p0) * INNER,
          g_olo + ((size_t)b * HW + p0) * INNER,
          tid, lane, mwarp, nwarp, acc);

    const int gid = lane >> 2, tig = lane & 3;
#pragma unroll
    for (int mt = 0; mt < 4; mt++) {
#pragma unroll
        for (int half = 0; half < 2; half++) {
            int c = mwarp + mt * 16 + gid + half * 8;
            float* dst = outp + ((size_t)b * C + c) * HW + p0;
#pragma unroll
            for (int nt = 0; nt < 4; nt++) {
                int col = nwarp + nt * 8 + 2 * tig;
                *(float2*)(dst + col) = make_float2(acc[mt * 4 + nt][half * 2],
                                                    acc[mt * 4 + nt][half * 2 + 1]);
            }
        }
    }
}

extern "C" void kernel_launch(void* const* d_in, const int* in_sizes, int n_in,
                              void* d_out, int out_size)
{
    const float* x     = (const float*)d_in[0];
    const float* wq    = (const float*)d_in[1];
    const float* wk    = (const float*)d_in[2];
    const float* wv    = (const float*)d_in[3];
    const float* wproj = (const float*)d_in[4];
    float* outp = (float*)d_out;

    cudaFuncSetAttribute(attn_kernel,
                         cudaFuncAttributeMaxDynamicSharedMemorySize, ATTN_SMEM);
    cudaFuncSetAttribute(qkv_mma_kernel,
                         cudaFuncAttributeMaxDynamicSharedMemorySize, GEMM_SMEM);
    cudaFuncSetAttribute(proj_mma_kernel,
                         cudaFuncAttributeMaxDynamicSharedMemorySize, GEMM_SMEM);

    wbake_kernel<<<dim3(64, 4), 256>>>(wq, wk, wv, wproj);
    xsplit_kernel<<<dim3(HW / 32, C / 32, BATCH), 256>>>(x);
    qkv_mma_kernel<<<dim3(NTILES, 3, BATCH), 256, GEMM_SMEM>>>();
    attn_kernel<<<dim3(W / TX, H / TY, HEADS * BATCH), 256, ATTN_SMEM>>>();
    proj_mma_kernel<<<dim3(NTILES, BATCH), 256, GEMM_SMEM>>>(outp);
}

// round 11
// speedup vs baseline: 1.0078x; 1.0017x over previous
#include <cuda_runtime.h>
#include <cuda_bf16.h>
#include <cstdint>

#define BATCH 2
#define C 128
#define H 96
#define W 96
#define HEADS 4
#define DHEAD 32
#define PAD 2
#define INNER 128
#define HW (H * W)
#define HP (H + 2 * PAD)
#define WP (W + 2 * PAD)
#define NTILES (HW / 128)   // 72

typedef unsigned long long u64;

// fp32 scratch
__device__ float g_q[(size_t)BATCH * HW * INNER];          // [b][p][inner]
__device__ float g_kpad[(size_t)BATCH * HP * WP * INNER];  // [b][yp][xp][inner]
__device__ float g_vpad[(size_t)BATCH * HP * WP * INNER];

// bf16 hi/lo operand images
__device__ __nv_bfloat16 g_xhi[(size_t)BATCH * HW * C];    // [b][p][c]
__device__ __nv_bfloat16 g_xlo[(size_t)BATCH * HW * C];
__device__ __nv_bfloat16 g_whi[4 * C * INNER];             // [mat][o][c]
__device__ __nv_bfloat16 g_wlo[4 * C * INNER];
__device__ __nv_bfloat16 g_ohi[(size_t)BATCH * HW * INNER];// [b][p][inner]
__device__ __nv_bfloat16 g_olo[(size_t)BATCH * HW * INNER];

#define FFMA2(d, a, b) \
    asm("fma.rn.f32x2 %0, %1, %2, %0;" : "+l"(d) : "l"(a), "l"(b))
#define PACK2(d, s) \
    asm("mov.b64 %0, {%1, %1};" : "=l"(d) : "f"(s))

__device__ __forceinline__ void cp16(uint32_t smem, const void* g) {
    asm volatile("cp.async.cg.shared.global [%0], [%1], 16;" :: "r"(smem), "l"(g));
}
#define CP_COMMIT() asm volatile("cp.async.commit_group;")
#define CP_WAIT(n)  asm volatile("cp.async.wait_group %0;" :: "n"(n))

__device__ __forceinline__ uint32_t smem_u32(const void* p) {
    uint32_t a;
    asm("{ .reg .u64 t; cvta.to.shared.u64 t, %1; cvt.u32.u64 %0, t; }"
        : "=r"(a) : "l"(p));
    return a;
}

// pack two f32 -> bf16x2 reg, v0 in low half (memory element 0)
#define PACK_BF16X2(res, v0, v1) \
    asm("cvt.rn.bf16x2.f32 %0, %1, %2;" : "=r"(res) : "f"(v1), "f"(v0))

#define LDM_X4(r, addr) \
    asm volatile("ldmatrix.sync.aligned.m8n8.x4.shared.b16 {%0,%1,%2,%3}, [%4];" \
        : "=r"((r)[0]), "=r"((r)[1]), "=r"((r)[2]), "=r"((r)[3]) : "r"(addr))

#define MMA16816(d, a, bp) \
    asm volatile("mma.sync.aligned.m16n8k16.row.col.f32.bf16.bf16.f32 " \
        "{%0,%1,%2,%3}, {%4,%5,%6,%7}, {%8,%9}, {%0,%1,%2,%3};" \
        : "+f"((d)[0]), "+f"((d)[1]), "+f"((d)[2]), "+f"((d)[3]) \
        : "r"((a)[0]), "r"((a)[1]), "r"((a)[2]), "r"((a)[3]), \
          "r"((bp)[0]), "r"((bp)[1]))

// smem tile: 128 rows x 128 bf16, row stride 272B (17*16 -> conflict-free)
#define TROW 272
#define TILE (128 * TROW)
#define GEMM_SMEM (3 * TILE)   // 104448 -> 2 blocks/SM

// ---------------------------------------------------------------------------
// Kernel A: split x (f32 [b][c][p]) -> g_xhi/g_xlo (bf16 [b][p][c])
// ---------------------------------------------------------------------------
__global__ __launch_bounds__(256) void xsplit_kernel(const float* __restrict__ x)
{
    __shared__ float t[32][33];
    const int p0 = blockIdx.x * 32, c0 = blockIdx.y * 32, b = blockIdx.z;
    const int tl = threadIdx.x & 31, th = threadIdx.x >> 5;
#pragma unroll
    for (int i = 0; i < 4; i++) {
        int c = th + i * 8;
        t[c][tl] = x[((size_t)b * C + c0 + c) * HW + p0 + tl];
    }
    __syncthreads();
#pragma unroll
    for (int i = 0; i < 4; i++) {
        int p = th + i * 8;
        float v = t[tl][p];
        __nv_bfloat16 hb = __float2bfloat16(v);
        float lov = v - __bfloat162float(hb);
        size_t off = ((size_t)b * HW + p0 + p) * C + c0 + tl;
        g_xhi[off] = hb;
        g_xlo[off] = __float2bfloat16(lov);
    }
}

// ---------------------------------------------------------------------------
// Kernel B: bake weights -> bf16 hi/lo [mat][o][c]
// ---------------------------------------------------------------------------
__global__ __launch_bounds__(256) void wbake_kernel(
    const float* __restrict__ wq, const float* __restrict__ wk,
    const float* __restrict__ wv, const float* __restrict__ wp)
{
    const int mat = blockIdx.y;
    const float* __restrict__ src =
        (mat == 0) ? wq : (mat == 1) ? wk : (mat == 2) ? wv : wp;
    int idx = blockIdx.x * 256 + threadIdx.x;
    float w = src[idx];
    __nv_bfloat16 hb = __float2bfloat16(w);
    float lov = w - __bfloat162float(hb);
    g_whi[mat * 16384 + idx] = hb;
    g_wlo[mat * 16384 + idx] = __float2bfloat16(lov);
}

// ---------------------------------------------------------------------------
// Shared HMMA mainloop (validated in R5)
// ---------------------------------------------------------------------------
__device__ __forceinline__ void mma_tiles(
    uint32_t Abase, uint32_t Bbase, int lane, int mwarp, int nwarp,
    float (*acc)[4])
{
    const uint32_t arow0 = Abase + (uint32_t)(mwarp + (lane & 15)) * TROW
                         + ((lane >> 4) & 1) * 16;
    const uint32_t brow0 = Bbase
                         + (uint32_t)(nwarp + ((lane >> 4) << 3) + (lane & 7)) * TROW
                         + ((lane >> 3) & 1) * 16;
#pragma unroll
    for (int k0 = 0; k0 < 8; k0++) {
        uint32_t a[4][4], bq[2][4];
#pragma unroll
        for (int mt = 0; mt < 4; mt++)
            LDM_X4(a[mt], arow0 + k0 * 32 + mt * (16 * TROW));
#pragma unroll
        for (int n2 = 0; n2 < 2; n2++)
            LDM_X4(bq[n2], brow0 + k0 * 32 + n2 * (16 * TROW));
#pragma unroll
        for (int mt = 0; mt < 4; mt++)
#pragma unroll
            for (int nt = 0; nt < 4; nt++)
                MMA16816(acc[mt * 4 + nt], a[mt], &bq[nt >> 1][(nt & 1) * 2]);
    }
}

__device__ __forceinline__ void stage_tile(
    uint32_t dst, const __nv_bfloat16* __restrict__ src, int tid)
{
    for (int i = tid; i < 2048; i += 256) {
        int r = i >> 4, ch = i & 15;
        cp16(dst + r * TROW + ch * 16, src + r * 128 + ch * 8);
    }
}

// 3-pass GEMM core with 3 smem buffers (Ahi, Bhi persistent; swap = Blo->Alo)
__device__ __forceinline__ void gemm3(
    uint32_t smb,
    const __nv_bfloat16* __restrict__ ah, const __nv_bfloat16* __restrict__ al,
    const __nv_bfloat16* __restrict__ bh, const __nv_bfloat16* __restrict__ bl,
    int tid, int lane, int mwarp, int nwarp, float (*acc)[4])
{
    const uint32_t AHI = smb, BHI = smb + TILE, SWP = smb + 2 * TILE;

    stage_tile(AHI, ah, tid);
    stage_tile(BHI, bh, tid);
    CP_COMMIT();
    stage_tile(SWP, bl, tid);
    CP_COMMIT();

    CP_WAIT(1);
    __syncthreads();
    mma_tiles(AHI, BHI, lane, mwarp, nwarp, acc);   // hi*hi
    CP_WAIT(0);
    __syncthreads();
    mma_tiles(AHI, SWP, lane, mwarp, nwarp, acc);   // hi*lo
    __syncthreads();                                 // SWP reads done
    stage_tile(SWP, al, tid);
    CP_COMMIT();
    CP_WAIT(0);
    __syncthreads();
    mma_tiles(SWP, BHI, lane, mwarp, nwarp, acc);   // lo*hi
}

// ---------------------------------------------------------------------------
// Kernel 1: QKV. A = X (pixels) hi/lo, B = W hi/lo. D[p][o].
// ---------------------------------------------------------------------------
__global__ __launch_bounds__(256) void qkv_mma_kernel()
{
    extern __shared__ char sm[];
    const uint32_t smb = smem_u32(sm);
    const int tid = threadIdx.x, wid = tid >> 5, lane = tid & 31;
    const int pb = blockIdx.x, mat = blockIdx.y, b = blockIdx.z;
    const int p0 = pb * 128;

    float acc[16][4];
#pragma unroll
    for (int i = 0; i < 16; i++)
#pragma unroll
        for (int j = 0; j < 4; j++) acc[i][j] = 0.f;

    const int mwarp = (wid >> 2) * 64, nwarp = (wid & 3) * 32;

    gemm3(smb,
          g_xhi + ((size_t)b * HW + p0) * C, g_xlo + ((size_t)b * HW + p0) * C,
          g_whi + mat * 16384, g_wlo + mat * 16384,
          tid, lane, mwarp, nwarp, acc);

    const int gid = lane >> 2, tig = lane & 3;
#pragma unroll
    for (int mt = 0; mt < 4; mt++) {
#pragma unroll
        for (int half = 0; half < 2; half++) {
            int r = mwarp + mt * 16 + gid + half * 8;
            int p = p0 + r;
            float* dst;
            if (mat == 0) {
                dst = g_q + ((size_t)b * HW + p) * INNER;
            } else {
                int yy = p / W, xx = p - yy * W;
                float* base = (mat == 1) ? g_kpad : g_vpad;
                dst = base + (((size_t)b * HP + yy + PAD) * WP + (xx + PAD)) * INNER;
            }
#pragma unroll
            for (int nt = 0; nt < 4; nt++) {
                int o = nwarp + nt * 8 + 2 * tig;
                *(float2*)(dst + o) = make_float2(acc[mt * 4 + nt][half * 2],
                                                  acc[mt * 4 + nt][half * 2 + 1]);
            }
        }
    }
}

// ---------------------------------------------------------------------------
// Kernel 2: window attention, pixel-pair + d-split, FUSED one-pass.
// Per tap: load k (8 regs), dot both pixels, shfl-join, exp, THEN load v
// into fresh staging and accumulate. No score arrays, no max pass
// (scores ~N(0,1): exp is safe; padded taps give exp(0)=1 like the ref).
// Serialized k->v staging keeps regs ~105 so ptxas can pipeline taps.
// ---------------------------------------------------------------------------
#define TX 32
#define TY 8
#define PWT (TX + 4)     // 36
#define PHT (TY + 4)     // 12
#define NPIX (PWT * PHT) // 432
#define DGS 433
#define ATTN_SMEM (2 * 8 * DGS * 16)   // 110848

__global__ __launch_bounds__(256, 2) void attn_kernel()
{
    extern __shared__ float4 sm4[];
    float4* ks4 = sm4;
    float4* vs4 = sm4 + 8 * DGS;
    const uint32_t smbk = smem_u32(ks4);
    const uint32_t smbv = smem_u32(vs4);

    const int t  = threadIdx.x;
    const int x0 = blockIdx.x * TX;
    const int y0 = blockIdx.y * TY;
    const int h  = blockIdx.z & 3;
    const int b  = blockIdx.z >> 2;

    const float* __restrict__ kg =
        g_kpad + (((size_t)b * HP + y0) * WP + x0) * INNER + h * DHEAD;
    const float* __restrict__ vg =
        g_vpad + (((size_t)b * HP + y0) * WP + x0) * INNER + h * DHEAD;

    // fill halo: pixel pp, channel group g (g = hh*4 + dgl) -> plane dgl*2+hh
#pragma unroll
    for (int i = t; i < NPIX * 8; i += 256) {
        int pp = i >> 3, g = i & 7;
        int py = pp / PWT, px = pp - py * PWT;
        int pl = ((g & 3) << 1) | (g >> 2);
        size_t goff = ((size_t)py * WP + px) * INNER + g * 4;
        cp16(smbk + (uint32_t)(pl * DGS + pp) * 16, kg + goff);
        cp16(smbv + (uint32_t)(pl * DGS + pp) * 16, vg + goff);
    }
    CP_COMMIT();

    const int hh   = t & 1;          // d-half
    const int pair = t >> 1;         // 0..127
    const int tx2  = pair & 15;      // pair column (pixels 2*tx2, 2*tx2+1)
    const int ty   = pair >> 4;      // 0..7
    const int p0p  = (y0 + ty) * W + x0 + 2 * tx2;

    // q (pre-scaled by 1/sqrt(32)) for both pixels, this d-half
    const float scale = 0.17677669529663687f;
    float q0f[16], q1f[16];
    {
        const float* qp0 = g_q + ((size_t)b * HW + p0p) * INNER + h * DHEAD + hh * 16;
        const float* qp1 = qp0 + INNER;
#pragma unroll
        for (int i = 0; i < 4; i++) {
            float4 v0 = *(const float4*)(qp0 + i * 4);
            float4 v1 = *(const float4*)(qp1 + i * 4);
            q0f[4 * i] = v0.x * scale; q0f[4 * i + 1] = v0.y * scale;
            q0f[4 * i + 2] = v0.z * scale; q0f[4 * i + 3] = v0.w * scale;
            q1f[4 * i] = v1.x * scale; q1f[4 * i + 1] = v1.y * scale;
            q1f[4 * i + 2] = v1.z * scale; q1f[4 * i + 3] = v1.w * scale;
        }
    }
    u64 q0[8], q1[8];
#pragma unroll
    for (int i = 0; i < 8; i++) {
        q0[i] = *(u64*)&q0f[2 * i];
        q1[i] = *(u64*)&q1f[2 * i];
    }

    CP_WAIT(0);
    __syncthreads();

    u64 o0[8], o1[8];
#pragma unroll
    for (int i = 0; i < 8; i++) { o0[i] = 0ull; o1[i] = 0ull; }
    float sum0 = 0.f, sum1 = 0.f;

#pragma unroll
    for (int di = 0; di < 5; di++) {
#pragma unroll
        for (int djj = 0; djj < 6; djj++) {
            const int pixi = (ty + di) * PWT + 2 * tx2 + djj;

            // ---- k phase ----
            u64 a0 = 0ull, a1 = 0ull, b0 = 0ull, b1 = 0ull;
#pragma unroll
            for (int dgl = 0; dgl < 4; dgl++) {
                ulonglong2 kq = *(const ulonglong2*)&ks4[(dgl * 2 + hh) * DGS + pixi];
                FFMA2(a0, q0[2 * dgl], kq.x);
                FFMA2(a1, q0[2 * dgl + 1], kq.y);
                FFMA2(b0, q1[2 * dgl], kq.x);
                FFMA2(b1, q1[2 * dgl + 1], kq.y);
            }
            float2 fa0 = *(float2*)&a0, fa1 = *(float2*)&a1;
            float2 fb0 = *(float2*)&b0, fb1 = *(float2*)&b1;
            float p0s = (fa0.x + fa0.y) + (fa1.x + fa1.y);
            float p1s = (fb0.x + fb0.y) + (fb1.x + fb1.y);
            p0s += __shfl_xor_sync(0xffffffffu, p0s, 1);
            p1s += __shfl_xor_sync(0xffffffffu, p1s, 1);

            u64 w0 = 0ull, w1 = 0ull;
            if (djj < 5) {
                float e = __expf(p0s);
                sum0 += e;
                PACK2(w0, e);
            }
            if (djj > 0) {
                float e = __expf(p1s);
                sum1 += e;
                PACK2(w1, e);
            }

            // ---- v phase (fresh staging; k staging dead by now) ----
#pragma unroll
            for (int dgl = 0; dgl < 4; dgl++) {
                ulonglong2 vq = *(const ulonglong2*)&vs4[(dgl * 2 + hh) * DGS + pixi];
                if (djj < 5) {
                    FFMA2(o0[2 * dgl], w0, vq.x);
                    FFMA2(o0[2 * dgl + 1], w0, vq.y);
                }
                if (djj > 0) {
                    FFMA2(o1[2 * dgl], w1, vq.x);
                    FFMA2(o1[2 * dgl + 1], w1, vq.y);
                }
            }
        }
    }

    const float inv0 = 1.f / sum0, inv1 = 1.f / sum1;

    // split to bf16 hi/lo and store both pixels' 16-channel halves
#pragma unroll
    for (int px = 0; px < 2; px++) {
        const u64* oo = px ? o1 : o0;
        const float inv = px ? inv1 : inv0;
        uint32_t hu[8], lu[8];
#pragma unroll
        for (int i = 0; i < 8; i++) {
            float2 f = *(float2*)&oo[i];
            float a = f.x * inv, bb = f.y * inv;
            __nv_bfloat16 ha = __float2bfloat16(a), hb = __float2bfloat16(bb);
            float la = a - __bfloat162float(ha);
            float lb = bb - __bfloat162float(hb);
            PACK_BF16X2(hu[i], a, bb);
            PACK_BF16X2(lu[i], la, lb);
        }
        __nv_bfloat16* oh = g_ohi + ((size_t)b * HW + p0p + px) * INNER + h * DHEAD + hh * 16;
        __nv_bfloat16* ol = g_olo + ((size_t)b * HW + p0p + px) * INNER + h * DHEAD + hh * 16;
#pragma unroll
        for (int cc = 0; cc < 2; cc++) {
            *(uint4*)(oh + cc * 8) = make_uint4(hu[4 * cc], hu[4 * cc + 1],
                                                hu[4 * cc + 2], hu[4 * cc + 3]);
            *(uint4*)(ol + cc * 8) = make_uint4(lu[4 * cc], lu[4 * cc + 1],
                                                lu[4 * cc + 2], lu[4 * cc + 3]);
        }
    }
}

// ---------------------------------------------------------------------------
// Kernel 3: proj. A = wproj hi/lo, B = attn-out hi/lo. D[c][p] -> NCHW.
// ---------------------------------------------------------------------------
__global__ __launch_bounds__(256) void proj_mma_kernel(float* __restrict__ outp)
{
    extern __shared__ char sm[];
    const uint32_t smb = smem_u32(sm);
    const int tid = threadIdx.x, wid = tid >> 5, lane = tid & 31;
    const int pb = blockIdx.x, b = blockIdx.y;
    const int p0 = pb * 128;

    float acc[16][4];
#pragma unroll
    for (int i = 0; i < 16; i++)
#pragma unroll
        for (int j = 0; j < 4; j++) acc[i][j] = 0.f;

    const int mwarp = (wid >> 2) * 64, nwarp = (wid & 3) * 32;

    gemm3(smb,
          g_whi + 3 * 16384, g_wlo + 3 * 16384,
          g_ohi + ((size_t)b * HW + p0) * INNER,
          g_olo + ((size_t)b * HW + p0) * INNER,
          tid, lane, mwarp, nwarp, acc);

    const int gid = lane >> 2, tig = lane & 3;
#pragma unroll
    for (int mt = 0; mt < 4; mt++) {
#pragma unroll
        for (int half = 0; half < 2; half++) {
            int c = mwarp + mt * 16 + gid + half * 8;
            float* dst = outp + ((size_t)b * C + c) * HW + p0;
#pragma unroll
            for (int nt = 0; nt < 4; nt++) {
                int col = nwarp + nt * 8 + 2 * tig;
                *(float2*)(dst + col) = make_float2(acc[mt * 4 + nt][half * 2],
                                                    acc[mt * 4 + nt][half * 2 + 1]);
            }
        }
    }
}

extern "C" void kernel_launch(void* const* d_in, const int* in_sizes, int n_in,
                              void* d_out, int out_size)
{
    const float* x     = (const float*)d_in[0];
    const float* wq    = (const float*)d_in[1];
    const float* wk    = (const float*)d_in[2];
    const float* wv    = (const float*)d_in[3];
    const float* wproj = (const float*)d_in[4];
    float* outp = (float*)d_out;

    cudaFuncSetAttribute(attn_kernel,
                         cudaFuncAttributeMaxDynamicSharedMemorySize, ATTN_SMEM);
    cudaFuncSetAttribute(qkv_mma_kernel,
                         cudaFuncAttributeMaxDynamicSharedMemorySize, GEMM_SMEM);
    cudaFuncSetAttribute(proj_mma_kernel,
                         cudaFuncAttributeMaxDynamicSharedMemorySize, GEMM_SMEM);

    wbake_kernel<<<dim3(64, 4), 256>>>(wq, wk, wv, wproj);
    xsplit_kernel<<<dim3(HW / 32, C / 32, BATCH), 256>>>(x);
    qkv_mma_kernel<<<dim3(NTILES, 3, BATCH), 256, GEMM_SMEM>>>();
    attn_kernel<<<dim3(W / TX, H / TY, HEADS * BATCH), 256, ATTN_SMEM>>>();
    proj_mma_kernel<<<dim3(NTILES, BATCH), 256, GEMM_SMEM>>>(outp);
}

// round 12
// speedup vs baseline: 1.2241x; 1.2146x over previous
#include <cuda_runtime.h>
#include <cuda_fp16.h>
#include <cstdint>

#define BATCH 2
#define C 128
#define H 96
#define W 96
#define HEADS 4
#define DHEAD 32
#define PAD 2
#define INNER 128
#define HW (H * W)
#define HP (H + 2 * PAD)
#define WP (W + 2 * PAD)
#define NTILES (HW / 128)   // 72

typedef unsigned long long u64;

// fp32 scratch
__device__ float g_q[(size_t)BATCH * HW * INNER];          // [b][p][inner]
__device__ float g_kpad[(size_t)BATCH * HP * WP * INNER];  // [b][yp][xp][inner]
__device__ float g_vpad[(size_t)BATCH * HP * WP * INNER];

// fp16 operand images
__device__ __half g_xh[(size_t)BATCH * HW * C];            // [b][p][c]  (hi only)
__device__ __half g_wh[4 * C * INNER];                     // [mat][o][c]
__device__ __half g_wl[4 * C * INNER];
__device__ __half g_oh[(size_t)BATCH * HW * INNER];        // [b][p][inner] (hi only)

#define FFMA2(d, a, b) \
    asm("fma.rn.f32x2 %0, %1, %2, %0;" : "+l"(d) : "l"(a), "l"(b))
#define PACK2(d, s) \
    asm("mov.b64 %0, {%1, %1};" : "=l"(d) : "f"(s))

__device__ __forceinline__ void cp16(uint32_t smem, const void* g) {
    asm volatile("cp.async.cg.shared.global [%0], [%1], 16;" :: "r"(smem), "l"(g));
}
#define CP_COMMIT() asm volatile("cp.async.commit_group;")
#define CP_WAIT(n)  asm volatile("cp.async.wait_group %0;" :: "n"(n))

__device__ __forceinline__ uint32_t smem_u32(const void* p) {
    uint32_t a;
    asm("{ .reg .u64 t; cvta.to.shared.u64 t, %1; cvt.u32.u64 %0, t; }"
        : "=r"(a) : "l"(p));
    return a;
}

// pack two f32 -> f16x2 reg, v0 in low half (memory element 0)
#define PACK_F16X2(res, v0, v1) \
    asm("cvt.rn.f16x2.f32 %0, %1, %2;" : "=r"(res) : "f"(v1), "f"(v0))

#define LDM_X4(r, addr) \
    asm volatile("ldmatrix.sync.aligned.m8n8.x4.shared.b16 {%0,%1,%2,%3}, [%4];" \
        : "=r"((r)[0]), "=r"((r)[1]), "=r"((r)[2]), "=r"((r)[3]) : "r"(addr))

#define MMA16816(d, a, bp) \
    asm volatile("mma.sync.aligned.m16n8k16.row.col.f32.f16.f16.f32 " \
        "{%0,%1,%2,%3}, {%4,%5,%6,%7}, {%8,%9}, {%0,%1,%2,%3};" \
        : "+f"((d)[0]), "+f"((d)[1]), "+f"((d)[2]), "+f"((d)[3]) \
        : "r"((a)[0]), "r"((a)[1]), "r"((a)[2]), "r"((a)[3]), \
          "r"((bp)[0]), "r"((bp)[1]))

// smem tile: 128 rows x 128 fp16, row stride 272B (17*16 -> conflict-free)
#define TROW 272
#define TILE (128 * TROW)
#define GEMM_SMEM (3 * TILE)   // 104448 -> 2 blocks/SM

// ---------------------------------------------------------------------------
// Kernel A: z<2: split x (f32 [b][c][p]) -> g_xh (fp16 [b][p][c]);
//           z==2: bake weights -> fp16 hi/lo [mat][o][c]  (merged wbake)
// ---------------------------------------------------------------------------
__global__ __launch_bounds__(256) void xsplit_kernel(
    const float* __restrict__ x,  const float* __restrict__ wq,
    const float* __restrict__ wk, const float* __restrict__ wv,
    const float* __restrict__ wp)
{
    if (blockIdx.z == 2) {
        int idx = (blockIdx.y * gridDim.x + blockIdx.x) * 256 + threadIdx.x;
        if (idx < 4 * C * INNER) {
            int mat = idx >> 14, e = idx & 16383;
            const float* __restrict__ src =
                (mat == 0) ? wq : (mat == 1) ? wk : (mat == 2) ? wv : wp;
            float w = src[e];
            __half hb = __float2half_rn(w);
            g_wh[idx] = hb;
            g_wl[idx] = __float2half_rn(w - __half2float(hb));
        }
        return;
    }
    __shared__ float t[32][33];
    const int p0 = blockIdx.x * 32, c0 = blockIdx.y * 32, b = blockIdx.z;
    const int tl = threadIdx.x & 31, th = threadIdx.x >> 5;
#pragma unroll
    for (int i = 0; i < 4; i++) {
        int c = th + i * 8;
        t[c][tl] = x[((size_t)b * C + c0 + c) * HW + p0 + tl];
    }
    __syncthreads();
#pragma unroll
    for (int i = 0; i < 4; i++) {
        int p = th + i * 8;
        g_xh[((size_t)b * HW + p0 + p) * C + c0 + tl] = __float2half_rn(t[tl][p]);
    }
}

// ---------------------------------------------------------------------------
// Shared HMMA mainloop (layout validated since R5; f16 frag layout identical)
// ---------------------------------------------------------------------------
__device__ __forceinline__ void mma_tiles(
    uint32_t Abase, uint32_t Bbase, int lane, int mwarp, int nwarp,
    float (*acc)[4])
{
    const uint32_t arow0 = Abase + (uint32_t)(mwarp + (lane & 15)) * TROW
                         + ((lane >> 4) & 1) * 16;
    const uint32_t brow0 = Bbase
                         + (uint32_t)(nwarp + ((lane >> 4) << 3) + (lane & 7)) * TROW
                         + ((lane >> 3) & 1) * 16;
#pragma unroll
    for (int k0 = 0; k0 < 8; k0++) {
        uint32_t a[4][4], bq[2][4];
#pragma unroll
        for (int mt = 0; mt < 4; mt++)
            LDM_X4(a[mt], arow0 + k0 * 32 + mt * (16 * TROW));
#pragma unroll
        for (int n2 = 0; n2 < 2; n2++)
            LDM_X4(bq[n2], brow0 + k0 * 32 + n2 * (16 * TROW));
#pragma unroll
        for (int mt = 0; mt < 4; mt++)
#pragma unroll
            for (int nt = 0; nt < 4; nt++)
                MMA16816(acc[mt * 4 + nt], a[mt], &bq[nt >> 1][(nt & 1) * 2]);
    }
}

__device__ __forceinline__ void stage_tile(
    uint32_t dst, const __half* __restrict__ src, int tid)
{
    for (int i = tid; i < 2048; i += 256) {
        int r = i >> 4, ch = i & 15;
        cp16(dst + r * TROW + ch * 16, src + r * 128 + ch * 8);
    }
}

// 2-pass GEMM: comm operand used in both passes; o1 pass1, o2 pass2.
// comm_is_A: comm is the A (row) operand; else comm is B.
__device__ __forceinline__ void gemm2(
    uint32_t smb,
    const __half* __restrict__ comm, const __half* __restrict__ o1,
    const __half* __restrict__ o2, bool comm_is_A,
    int tid, int lane, int mwarp, int nwarp, float (*acc)[4])
{
    const uint32_t S0 = smb, S1 = smb + TILE, S2 = smb + 2 * TILE;

    stage_tile(S0, comm, tid);
    stage_tile(S1, o1, tid);
    CP_COMMIT();
    stage_tile(S2, o2, tid);
    CP_COMMIT();

    CP_WAIT(1);
    __syncthreads();
    if (comm_is_A) mma_tiles(S0, S1, lane, mwarp, nwarp, acc);
    else           mma_tiles(S1, S0, lane, mwarp, nwarp, acc);
    CP_WAIT(0);
    __syncthreads();
    if (comm_is_A) mma_tiles(S0, S2, lane, mwarp, nwarp, acc);
    else           mma_tiles(S2, S0, lane, mwarp, nwarp, acc);
}

// ---------------------------------------------------------------------------
// Kernel 1: QKV. D[p][o] = Xh[p][c] * (Wh + Wl)[o][c].
// ---------------------------------------------------------------------------
__global__ __launch_bounds__(256) void qkv_mma_kernel()
{
    extern __shared__ char sm[];
    const uint32_t smb = smem_u32(sm);
    const int tid = threadIdx.x, wid = tid >> 5, lane = tid & 31;
    const int pb = blockIdx.x, mat = blockIdx.y, b = blockIdx.z;
    const int p0 = pb * 128;

    float acc[16][4];
#pragma unroll
    for (int i = 0; i < 16; i++)
#pragma unroll
        for (int j = 0; j < 4; j++) acc[i][j] = 0.f;

    const int mwarp = (wid >> 2) * 64, nwarp = (wid & 3) * 32;

    gemm2(smb,
          g_xh + ((size_t)b * HW + p0) * C,          // A (common)
          g_wh + mat * 16384, g_wl + mat * 16384,    // B passes
          true, tid, lane, mwarp, nwarp, acc);

    const int gid = lane >> 2, tig = lane & 3;
#pragma unroll
    for (int mt = 0; mt < 4; mt++) {
#pragma unroll
        for (int half = 0; half < 2; half++) {
            int r = mwarp + mt * 16 + gid + half * 8;
            int p = p0 + r;
            float* dst;
            if (mat == 0) {
                dst = g_q + ((size_t)b * HW + p) * INNER;
            } else {
                int yy = p / W, xx = p - yy * W;
                float* base = (mat == 1) ? g_kpad : g_vpad;
                dst = base + (((size_t)b * HP + yy + PAD) * WP + (xx + PAD)) * INNER;
            }
#pragma unroll
            for (int nt = 0; nt < 4; nt++) {
                int o = nwarp + nt * 8 + 2 * tig;
                *(float2*)(dst + o) = make_float2(acc[mt * 4 + nt][half * 2],
                                                  acc[mt * 4 + nt][half * 2 + 1]);
            }
        }
    }
}

// ---------------------------------------------------------------------------
// Kernel 2: window attention, pixel-pair + d-split, fused one-pass (R11).
// Epilogue now emits single fp16 image (no lo split).
// ---------------------------------------------------------------------------
#define TX 32
#define TY 8
#define PWT (TX + 4)     // 36
#define PHT (TY + 4)     // 12
#define NPIX (PWT * PHT) // 432
#define DGS 433
#define ATTN_SMEM (2 * 8 * DGS * 16)   // 110848

__global__ __launch_bounds__(256, 2) void attn_kernel()
{
    extern __shared__ float4 sm4[];
    float4* ks4 = sm4;
    float4* vs4 = sm4 + 8 * DGS;
    const uint32_t smbk = smem_u32(ks4);
    const uint32_t smbv = smem_u32(vs4);

    const int t  = threadIdx.x;
    const int x0 = blockIdx.x * TX;
    const int y0 = blockIdx.y * TY;
    const int h  = blockIdx.z & 3;
    const int b  = blockIdx.z >> 2;

    const float* __restrict__ kg =
        g_kpad + (((size_t)b * HP + y0) * WP + x0) * INNER + h * DHEAD;
    const float* __restrict__ vg =
        g_vpad + (((size_t)b * HP + y0) * WP + x0) * INNER + h * DHEAD;

#pragma unroll
    for (int i = t; i < NPIX * 8; i += 256) {
        int pp = i >> 3, g = i & 7;
        int py = pp / PWT, px = pp - py * PWT;
        int pl = ((g & 3) << 1) | (g >> 2);
        size_t goff = ((size_t)py * WP + px) * INNER + g * 4;
        cp16(smbk + (uint32_t)(pl * DGS + pp) * 16, kg + goff);
        cp16(smbv + (uint32_t)(pl * DGS + pp) * 16, vg + goff);
    }
    CP_COMMIT();

    const int hh   = t & 1;          // d-half
    const int pair = t >> 1;         // 0..127
    const int tx2  = pair & 15;      // pair column (pixels 2*tx2, 2*tx2+1)
    const int ty   = pair >> 4;      // 0..7
    const int p0p  = (y0 + ty) * W + x0 + 2 * tx2;

    const float scale = 0.17677669529663687f;  // 1/sqrt(32)
    float q0f[16], q1f[16];
    {
        const float* qp0 = g_q + ((size_t)b * HW + p0p) * INNER + h * DHEAD + hh * 16;
        const float* qp1 = qp0 + INNER;
#pragma unroll
        for (int i = 0; i < 4; i++) {
            float4 v0 = *(const float4*)(qp0 + i * 4);
            float4 v1 = *(const float4*)(qp1 + i * 4);
            q0f[4 * i] = v0.x * scale; q0f[4 * i + 1] = v0.y * scale;
            q0f[4 * i + 2] = v0.z * scale; q0f[4 * i + 3] = v0.w * scale;
            q1f[4 * i] = v1.x * scale; q1f[4 * i + 1] = v1.y * scale;
            q1f[4 * i + 2] = v1.z * scale; q1f[4 * i + 3] = v1.w * scale;
        }
    }
    u64 q0[8], q1[8];
#pragma unroll
    for (int i = 0; i < 8; i++) {
        q0[i] = *(u64*)&q0f[2 * i];
        q1[i] = *(u64*)&q1f[2 * i];
    }

    CP_WAIT(0);
    __syncthreads();

    u64 o0[8], o1[8];
#pragma unroll
    for (int i = 0; i < 8; i++) { o0[i] = 0ull; o1[i] = 0ull; }
    float sum0 = 0.f, sum1 = 0.f;

#pragma unroll
    for (int di = 0; di < 5; di++) {
#pragma unroll
        for (int djj = 0; djj < 6; djj++) {
            const int pixi = (ty + di) * PWT + 2 * tx2 + djj;

            // ---- k phase ----
            u64 a0 = 0ull, a1 = 0ull, b0 = 0ull, b1 = 0ull;
#pragma unroll
            for (int dgl = 0; dgl < 4; dgl++) {
                ulonglong2 kq = *(const ulonglong2*)&ks4[(dgl * 2 + hh) * DGS + pixi];
                FFMA2(a0, q0[2 * dgl], kq.x);
                FFMA2(a1, q0[2 * dgl + 1], kq.y);
                FFMA2(b0, q1[2 * dgl], kq.x);
                FFMA2(b1, q1[2 * dgl + 1], kq.y);
            }
            float2 fa0 = *(float2*)&a0, fa1 = *(float2*)&a1;
            float2 fb0 = *(float2*)&b0, fb1 = *(float2*)&b1;
            float p0s = (fa0.x + fa0.y) + (fa1.x + fa1.y);
            float p1s = (fb0.x + fb0.y) + (fb1.x + fb1.y);
            p0s += __shfl_xor_sync(0xffffffffu, p0s, 1);
            p1s += __shfl_xor_sync(0xffffffffu, p1s, 1);

            u64 w0 = 0ull, w1 = 0ull;
            if (djj < 5) {
                float e = __expf(p0s);
                sum0 += e;
                PACK2(w0, e);
            }
            if (djj > 0) {
                float e = __expf(p1s);
                sum1 += e;
                PACK2(w1, e);
            }

            // ---- v phase ----
#pragma unroll
            for (int dgl = 0; dgl < 4; dgl++) {
                ulonglong2 vq = *(const ulonglong2*)&vs4[(dgl * 2 + hh) * DGS + pixi];
                if (djj < 5) {
                    FFMA2(o0[2 * dgl], w0, vq.x);
                    FFMA2(o0[2 * dgl + 1], w0, vq.y);
                }
                if (djj > 0) {
                    FFMA2(o1[2 * dgl], w1, vq.x);
                    FFMA2(o1[2 * dgl + 1], w1, vq.y);
                }
            }
        }
    }

    const float inv0 = 1.f / sum0, inv1 = 1.f / sum1;

    // store both pixels' 16-channel halves as fp16 (hi only)
#pragma unroll
    for (int px = 0; px < 2; px++) {
        const u64* oo = px ? o1 : o0;
        const float inv = px ? inv1 : inv0;
        uint32_t hu[8];
#pragma unroll
        for (int i = 0; i < 8; i++) {
            float2 f = *(float2*)&oo[i];
            PACK_F16X2(hu[i], f.x * inv, f.y * inv);
        }
        __half* oh = g_oh + ((size_t)b * HW + p0p + px) * INNER + h * DHEAD + hh * 16;
        *(uint4*)(oh)     = make_uint4(hu[0], hu[1], hu[2], hu[3]);
        *(uint4*)(oh + 8) = make_uint4(hu[4], hu[5], hu[6], hu[7]);
    }
}

// ---------------------------------------------------------------------------
// Kernel 3: proj. D[c][p] = (Wph + Wpl)[c][i] * Oh[p][i]. -> NCHW.
// ---------------------------------------------------------------------------
__global__ __launch_bounds__(256) void proj_mma_kernel(float* __restrict__ outp)
{
    extern __shared__ char sm[];
    const uint32_t smb = smem_u32(sm);
    const int tid = threadIdx.x, wid = tid >> 5, lane = tid & 31;
    const int pb = blockIdx.x, b = blockIdx.y;
    const int p0 = pb * 128;

    float acc[16][4];
#pragma unroll
    for (int i = 0; i < 16; i++)
#pragma unroll
        for (int j = 0; j < 4; j++) acc[i][j] = 0.f;

    const int mwarp = (wid >> 2) * 64, nwarp = (wid & 3) * 32;

    gemm2(smb,
          g_oh + ((size_t)b * HW + p0) * INNER,      // B (common)
          g_wh + 3 * 16384, g_wl + 3 * 16384,        // A passes
          false, tid, lane, mwarp, nwarp, acc);

    const int gid = lane >> 2, tig = lane & 3;
#pragma unroll
    for (int mt = 0; mt < 4; mt++) {
#pragma unroll
        for (int half = 0; half < 2; half++) {
            int c = mwarp + mt * 16 + gid + half * 8;
            float* dst = outp + ((size_t)b * C + c) * HW + p0;
#pragma unroll
            for (int nt = 0; nt < 4; nt++) {
                int col = nwarp + nt * 8 + 2 * tig;
                *(float2*)(dst + col) = make_float2(acc[mt * 4 + nt][half * 2],
                                                    acc[mt * 4 + nt][half * 2 + 1]);
            }
        }
    }
}

extern "C" void kernel_launch(void* const* d_in, const int* in_sizes, int n_in,
                              void* d_out, int out_size)
{
    const float* x     = (const float*)d_in[0];
    const float* wq    = (const float*)d_in[1];
    const float* wk    = (const float*)d_in[2];
    const float* wv    = (const float*)d_in[3];
    const float* wproj = (const float*)d_in[4];
    float* outp = (float*)d_out;

    cudaFuncSetAttribute(attn_kernel,
                         cudaFuncAttributeMaxDynamicSharedMemorySize, ATTN_SMEM);
    cudaFuncSetAttribute(qkv_mma_kernel,
                         cudaFuncAttributeMaxDynamicSharedMemorySize, GEMM_SMEM);
    cudaFuncSetAttribute(proj_mma_kernel,
                         cudaFuncAttributeMaxDynamicSharedMemorySize, GEMM_SMEM);

    xsplit_kernel<<<dim3(HW / 32, C / 32, 3), 256>>>(x, wq, wk, wv, wproj);
    qkv_mma_kernel<<<dim3(NTILES, 3, BATCH), 256, GEMM_SMEM>>>();
    attn_kernel<<<dim3(W / TX, H / TY, HEADS * BATCH), 256, ATTN_SMEM>>>();
    proj_mma_kernel<<<dim3(NTILES, BATCH), 256, GEMM_SMEM>>>(outp);
}

// round 13
// speedup vs baseline: 1.5374x; 1.2560x over previous
#include <cuda_runtime.h>
#include <cuda_fp16.h>
#include <cstdint>

#define BATCH 2
#define C 128
#define H 96
#define W 96
#define HEADS 4
#define DHEAD 32
#define PAD 2
#define INNER 128
#define HW (H * W)
#define HP (H + 2 * PAD)
#define WP (W + 2 * PAD)
#define NTILES (HW / 128)   // 72

typedef unsigned long long u64;

// fp32 scratch
__device__ float g_q[(size_t)BATCH * HW * INNER];            // [b][p][inner]
// plane-major k/v: [b][h][g(8)][yp][xp] float4 (padding stays zero)
__device__ float4 g_kpad4[(size_t)BATCH * HEADS * 8 * HP * WP];
__device__ float4 g_vpad4[(size_t)BATCH * HEADS * 8 * HP * WP];

// fp16 operand images, PRE-SWIZZLED: half (row, c) at row*128 + ((c>>3)^(row&7))*8 + (c&7)
__device__ __half g_xh[(size_t)BATCH * HW * C];              // rows = pixels
__device__ __half g_wh[4 * C * INNER];                       // rows = out-ch
__device__ __half g_wl[4 * C * INNER];
__device__ __half g_oh[(size_t)BATCH * HW * INNER];          // rows = pixels

#define FFMA2(d, a, b) \
    asm("fma.rn.f32x2 %0, %1, %2, %0;" : "+l"(d) : "l"(a), "l"(b))
#define PACK2(d, s) \
    asm("mov.b64 %0, {%1, %1};" : "=l"(d) : "f"(s))

__device__ __forceinline__ uint32_t smem_u32(const void* p) {
    uint32_t a;
    asm("{ .reg .u64 t; cvta.to.shared.u64 t, %1; cvt.u32.u64 %0, t; }"
        : "=r"(a) : "l"(p));
    return a;
}

#define MBARRIER_INIT(mb, n) \
    asm volatile("mbarrier.init.shared.b64 [%0], %1;" :: "r"((uint32_t)(mb)), "r"((uint32_t)(n)) : "memory")
#define MBARRIER_EXPECT_TX(mb, bytes) \
    asm volatile("mbarrier.arrive.expect_tx.shared.b64 _, [%0], %1;" \
                 :: "r"((uint32_t)(mb)), "r"((uint32_t)(bytes)) : "memory")
#define MBARRIER_WAIT_PARITY(mb, ph) do {                                         \
    uint32_t _mb = (uint32_t)(mb); uint32_t _ph = (uint32_t)(ph); uint32_t _done; \
    asm volatile("{ .reg .pred p; mbarrier.try_wait.parity.acquire.cta.shared::cta.b64 p, [%1], %2; selp.b32 %0, 1, 0, p; }" \
                 : "=r"(_done) : "r"(_mb), "r"(_ph) : "memory");                  \
    if (!_done) {                                                                 \
        asm volatile("{ .reg .pred P1; WL_%=: mbarrier.try_wait.parity.acquire.cta.shared::cta.b64 P1, [%0], %1, 0x989680; @P1 bra.uni WD_%=; bra.uni WL_%=; WD_%=: }" \
                     :: "r"(_mb), "r"(_ph) : "memory");                           \
    } } while (0)

#define BULK_G2S(dst, src, bytes, mbar) \
    asm volatile("cp.async.bulk.shared::cluster.global.mbarrier::complete_tx::bytes [%0], [%1], %2, [%3];" \
        :: "r"((uint32_t)(dst)), "l"(src), "r"((uint32_t)(bytes)), "r"((uint32_t)(mbar)) : "memory")

// pack two f32 -> f16x2 reg, v0 in low half (memory element 0)
#define PACK_F16X2(res, v0, v1) \
    asm("cvt.rn.f16x2.f32 %0, %1, %2;" : "=r"(res) : "f"(v1), "f"(v0))

#define LDM_X4(r, addr) \
    asm volatile("ldmatrix.sync.aligned.m8n8.x4.shared.b16 {%0,%1,%2,%3}, [%4];" \
        : "=r"((r)[0]), "=r"((r)[1]), "=r"((r)[2]), "=r"((r)[3]) : "r"(addr))

#define MMA16816(d, a, bp) \
    asm volatile("mma.sync.aligned.m16n8k16.row.col.f32.f16.f16.f32 " \
        "{%0,%1,%2,%3}, {%4,%5,%6,%7}, {%8,%9}, {%0,%1,%2,%3};" \
        : "+f"((d)[0]), "+f"((d)[1]), "+f"((d)[2]), "+f"((d)[3]) \
        : "r"((a)[0]), "r"((a)[1]), "r"((a)[2]), "r"((a)[3]), \
          "r"((bp)[0]), "r"((bp)[1]))

// GEMM smem: 3 dense 32KB tiles (256B rows, XOR-swizzled images) + 2 mbarriers
#define TILE 32768
#define GEMM_SMEM (3 * TILE + 32)

// swizzled half-index within a row: chunk (c>>3) ^ (row&7), sub c&7
__device__ __forceinline__ int sw_idx(int row, int c) {
    return (((c >> 3) ^ (row & 7)) << 3) + (c & 7);
}

// ---------------------------------------------------------------------------
// Kernel A: z<2: split x -> g_xh (fp16 [p][c], swizzled); z==2: bake weights
// ---------------------------------------------------------------------------
__global__ __launch_bounds__(256) void xsplit_kernel(
    const float* __restrict__ x,  const float* __restrict__ wq,
    const float* __restrict__ wk, const float* __restrict__ wv,
    const float* __restrict__ wp)
{
    if (blockIdx.z == 2) {
        int idx = (blockIdx.y * gridDim.x + blockIdx.x) * 256 + threadIdx.x;
        if (idx < 4 * C * INNER) {
            int mat = idx >> 14, e = idx & 16383;
            const float* __restrict__ src =
                (mat == 0) ? wq : (mat == 1) ? wk : (mat == 2) ? wv : wp;
            float w = src[e];
            int o = e >> 7, c = e & 127;
            __half hb = __float2half_rn(w);
            size_t off = (size_t)mat * 16384 + o * 128 + sw_idx(o, c);
            g_wh[off] = hb;
            g_wl[off] = __float2half_rn(w - __half2float(hb));
        }
        return;
    }
    __shared__ float t[32][33];
    const int p0 = blockIdx.x * 32, c0 = blockIdx.y * 32, b = blockIdx.z;
    const int tl = threadIdx.x & 31, th = threadIdx.x >> 5;
#pragma unroll
    for (int i = 0; i < 4; i++) {
        int c = th + i * 8;
        t[c][tl] = x[((size_t)b * C + c0 + c) * HW + p0 + tl];
    }
    __syncthreads();
#pragma unroll
    for (int i = 0; i < 4; i++) {
        int p = th + i * 8;
        int P = p0 + p, c = c0 + tl;
        g_xh[((size_t)b * HW + P) * C + sw_idx(P, c)] = __float2half_rn(t[tl][p]);
    }
}

// ---------------------------------------------------------------------------
// HMMA mainloop on dense 256B-row tiles with XOR swizzle
// ---------------------------------------------------------------------------
__device__ __forceinline__ void mma_tiles(
    uint32_t Abase, uint32_t Bbase, int lane, int mwarp, int nwarp,
    float (*acc)[4])
{
    const int xr = lane & 7;
    const uint32_t arowb = Abase + (uint32_t)(mwarp + (lane & 15)) * 256;
    const int ac0 = (lane >> 4) & 1;
    const uint32_t browb = Bbase
                         + (uint32_t)(nwarp + ((lane >> 4) << 3) + (lane & 7)) * 256;
    const int bc0 = (lane >> 3) & 1;
#pragma unroll
    for (int k0 = 0; k0 < 8; k0++) {
        const uint32_t aoff = (uint32_t)(((k0 * 2 + ac0) ^ xr) << 4);
        const uint32_t boff = (uint32_t)(((k0 * 2 + bc0) ^ xr) << 4);
        uint32_t a[4][4], bq[2][4];
#pragma unroll
        for (int mt = 0; mt < 4; mt++)
            LDM_X4(a[mt], arowb + mt * (16 * 256) + aoff);
#pragma unroll
        for (int n2 = 0; n2 < 2; n2++)
            LDM_X4(bq[n2], browb + n2 * (16 * 256) + boff);
#pragma unroll
        for (int mt = 0; mt < 4; mt++)
#pragma unroll
            for (int nt = 0; nt < 4; nt++)
                MMA16816(acc[mt * 4 + nt], a[mt], &bq[nt >> 1][(nt & 1) * 2]);
    }
}

// 2-pass GEMM with bulk staging: S0=comm, S1=o1, S2=o2
__device__ __forceinline__ void gemm2(
    uint32_t smb,
    const __half* __restrict__ comm, const __half* __restrict__ o1,
    const __half* __restrict__ o2, bool comm_is_A,
    int tid, int lane, int mwarp, int nwarp, float (*acc)[4])
{
    const uint32_t S0 = smb, S1 = smb + TILE, S2 = smb + 2 * TILE;
    const uint32_t MB0 = smb + 3 * TILE, MB1 = MB0 + 8;

    if (tid == 0) { MBARRIER_INIT(MB0, 2); MBARRIER_INIT(MB1, 1); }
    __syncthreads();
    if (tid == 0)       { MBARRIER_EXPECT_TX(MB0, TILE); BULK_G2S(S0, comm, TILE, MB0); }
    else if (tid == 32) { MBARRIER_EXPECT_TX(MB0, TILE); BULK_G2S(S1, o1, TILE, MB0); }
    else if (tid == 64) { MBARRIER_EXPECT_TX(MB1, TILE); BULK_G2S(S2, o2, TILE, MB1); }

    MBARRIER_WAIT_PARITY(MB0, 0);
    if (comm_is_A) mma_tiles(S0, S1, lane, mwarp, nwarp, acc);
    else           mma_tiles(S1, S0, lane, mwarp, nwarp, acc);
    MBARRIER_WAIT_PARITY(MB1, 0);
    if (comm_is_A) mma_tiles(S0, S2, lane, mwarp, nwarp, acc);
    else           mma_tiles(S2, S0, lane, mwarp, nwarp, acc);
}

// ---------------------------------------------------------------------------
// Kernel 1: QKV. D[p][o] = Xh[p][c] * (Wh + Wl)[o][c].
// k/v outputs go to plane-major g_kpad4/g_vpad4.
// ---------------------------------------------------------------------------
__global__ __launch_bounds__(256) void qkv_mma_kernel()
{
    extern __shared__ char sm[];
    const uint32_t smb = smem_u32(sm);
    const int tid = threadIdx.x, wid = tid >> 5, lane = tid & 31;
    const int pb = blockIdx.x, mat = blockIdx.y, b = blockIdx.z;
    const int p0 = pb * 128;

    float acc[16][4];
#pragma unroll
    for (int i = 0; i < 16; i++)
#pragma unroll
        for (int j = 0; j < 4; j++) acc[i][j] = 0.f;

    const int mwarp = (wid >> 2) * 64, nwarp = (wid & 3) * 32;

    gemm2(smb,
          g_xh + ((size_t)b * HW + p0) * C,
          g_wh + mat * 16384, g_wl + mat * 16384,
          true, tid, lane, mwarp, nwarp, acc);

    const int gid = lane >> 2, tig = lane & 3;
#pragma unroll
    for (int mt = 0; mt < 4; mt++) {
#pragma unroll
        for (int half = 0; half < 2; half++) {
            int r = mwarp + mt * 16 + gid + half * 8;
            int p = p0 + r;
            if (mat == 0) {
                float* dst = g_q + ((size_t)b * HW + p) * INNER;
#pragma unroll
                for (int nt = 0; nt < 4; nt++) {
                    int o = nwarp + nt * 8 + 2 * tig;
                    *(float2*)(dst + o) = make_float2(acc[mt * 4 + nt][half * 2],
                                                      acc[mt * 4 + nt][half * 2 + 1]);
                }
            } else {
                int yy = p / W, xx = p - yy * W;
                float4* base = (mat == 1) ? g_kpad4 : g_vpad4;
#pragma unroll
                for (int nt = 0; nt < 4; nt++) {
                    int c = nwarp + nt * 8 + 2 * tig;
                    int h = c >> 5, g = (c >> 2) & 7, sub = c & 3;
                    float* dst = (float*)(base
                        + ((((size_t)(b * HEADS + h) * 8 + g) * HP + yy + PAD) * WP
                           + xx + PAD)) + sub;
                    *(float2*)dst = make_float2(acc[mt * 4 + nt][half * 2],
                                                acc[mt * 4 + nt][half * 2 + 1]);
                }
            }
        }
    }
}

// ---------------------------------------------------------------------------
// Kernel 2: window attention (R11/R12 fused one-pass), bulk-staged halo.
// ---------------------------------------------------------------------------
#define TX 32
#define TY 8
#define PWT (TX + 4)     // 36
#define PHT (TY + 4)     // 12
#define DGS 433
#define ATTN_SMEM (2 * 8 * DGS * 16 + 16)   // + mbarrier

__global__ __launch_bounds__(256, 2) void attn_kernel()
{
    extern __shared__ float4 sm4[];
    float4* ks4 = sm4;
    float4* vs4 = sm4 + 8 * DGS;
    const uint32_t smbk = smem_u32(ks4);
    const uint32_t smbv = smem_u32(vs4);
    const uint32_t MB = smbk + 2 * 8 * DGS * 16;

    const int t  = threadIdx.x;
    const int x0 = blockIdx.x * TX;
    const int y0 = blockIdx.y * TY;
    const int h  = blockIdx.z & 3;
    const int b  = blockIdx.z >> 2;

    if (t == 0) MBARRIER_INIT(MB, 192);
    __syncthreads();

    // 192 bulk copies: 2(kv) x 8 planes x 12 rows, 576B each
    if (t < 192) {
        int kv = t >= 96;
        int j  = t - kv * 96;
        int pl = j / 12, py = j - pl * 12;
        int gsrc = (pl & 1) * 4 + (pl >> 1);
        const float4* src = (kv ? g_vpad4 : g_kpad4)
            + (((size_t)(b * HEADS + h) * 8 + gsrc) * HP + y0 + py) * WP + x0;
        uint32_t dst = (kv ? smbv : smbk) + (uint32_t)(pl * DGS + py * PWT) * 16;
        MBARRIER_EXPECT_TX(MB, 576);
        BULK_G2S(dst, src, 576, MB);
    }

    const int hh   = t & 1;          // d-half
    const int pair = t >> 1;         // 0..127
    const int tx2  = pair & 15;
    const int ty   = pair >> 4;
    const int p0p  = (y0 + ty) * W + x0 + 2 * tx2;

    const float scale = 0.17677669529663687f;  // 1/sqrt(32)
    float q0f[16], q1f[16];
    {
        const float* qp0 = g_q + ((size_t)b * HW + p0p) * INNER + h * DHEAD + hh * 16;
        const float* qp1 = qp0 + INNER;
#pragma unroll
        for (int i = 0; i < 4; i++) {
            float4 v0 = *(const float4*)(qp0 + i * 4);
            float4 v1 = *(const float4*)(qp1 + i * 4);
            q0f[4 * i] = v0.x * scale; q0f[4 * i + 1] = v0.y * scale;
            q0f[4 * i + 2] = v0.z * scale; q0f[4 * i + 3] = v0.w * scale;
            q1f[4 * i] = v1.x * scale; q1f[4 * i + 1] = v1.y * scale;
            q1f[4 * i + 2] = v1.z * scale; q1f[4 * i + 3] = v1.w * scale;
        }
    }
    u64 q0[8], q1[8];
#pragma unroll
    for (int i = 0; i < 8; i++) {
        q0[i] = *(u64*)&q0f[2 * i];
        q1[i] = *(u64*)&q1f[2 * i];
    }

    MBARRIER_WAIT_PARITY(MB, 0);
    __syncthreads();

    u64 o0[8], o1[8];
#pragma unroll
    for (int i = 0; i < 8; i++) { o0[i] = 0ull; o1[i] = 0ull; }
    float sum0 = 0.f, sum1 = 0.f;

#pragma unroll
    for (int di = 0; di < 5; di++) {
#pragma unroll
        for (int djj = 0; djj < 6; djj++) {
            const int pixi = (ty + di) * PWT + 2 * tx2 + djj;

            u64 a0 = 0ull, a1 = 0ull, b0 = 0ull, b1 = 0ull;
#pragma unroll
            for (int dgl = 0; dgl < 4; dgl++) {
                ulonglong2 kq = *(const ulonglong2*)&ks4[(dgl * 2 + hh) * DGS + pixi];
                FFMA2(a0, q0[2 * dgl], kq.x);
                FFMA2(a1, q0[2 * dgl + 1], kq.y);
                FFMA2(b0, q1[2 * dgl], kq.x);
                FFMA2(b1, q1[2 * dgl + 1], kq.y);
            }
            float2 fa0 = *(float2*)&a0, fa1 = *(float2*)&a1;
            float2 fb0 = *(float2*)&b0, fb1 = *(float2*)&b1;
            float p0s = (fa0.x + fa0.y) + (fa1.x + fa1.y);
            float p1s = (fb0.x + fb0.y) + (fb1.x + fb1.y);
            p0s += __shfl_xor_sync(0xffffffffu, p0s, 1);
            p1s += __shfl_xor_sync(0xffffffffu, p1s, 1);

            u64 w0 = 0ull, w1 = 0ull;
            if (djj < 5) {
                float e = __expf(p0s);
                sum0 += e;
                PACK2(w0, e);
            }
            if (djj > 0) {
                float e = __expf(p1s);
                sum1 += e;
                PACK2(w1, e);
            }

#pragma unroll
            for (int dgl = 0; dgl < 4; dgl++) {
                ulonglong2 vq = *(const ulonglong2*)&vs4[(dgl * 2 + hh) * DGS + pixi];
                if (djj < 5) {
                    FFMA2(o0[2 * dgl], w0, vq.x);
                    FFMA2(o0[2 * dgl + 1], w0, vq.y);
                }
                if (djj > 0) {
                    FFMA2(o1[2 * dgl], w1, vq.x);
                    FFMA2(o1[2 * dgl + 1], w1, vq.y);
                }
            }
        }
    }

    const float inv0 = 1.f / sum0, inv1 = 1.f / sum1;

    // store fp16, swizzled image: chunks (h*4+hh*2+{0,1}) ^ (P&7)
#pragma unroll
    for (int px = 0; px < 2; px++) {
        const u64* oo = px ? o1 : o0;
        const float inv = px ? inv1 : inv0;
        uint32_t hu[8];
#pragma unroll
        for (int i = 0; i < 8; i++) {
            float2 f = *(float2*)&oo[i];
            PACK_F16X2(hu[i], f.x * inv, f.y * inv);
        }
        const int P = p0p + px;
        __half* rowp = g_oh + ((size_t)b * HW + P) * INNER;
        const int cb = h * 4 + hh * 2, xr = P & 7;
        *(uint4*)(rowp + ((cb ^ xr) << 3))       = make_uint4(hu[0], hu[1], hu[2], hu[3]);
        *(uint4*)(rowp + (((cb + 1) ^ xr) << 3)) = make_uint4(hu[4], hu[5], hu[6], hu[7]);
    }
}

// ---------------------------------------------------------------------------
// Kernel 3: proj. D[c][p] = (Wph + Wpl)[c][i] * Oh[p][i]. -> NCHW.
// ---------------------------------------------------------------------------
__global__ __launch_bounds__(256) void proj_mma_kernel(float* __restrict__ outp)
{
    extern __shared__ char sm[];
    const uint32_t smb = smem_u32(sm);
    const int tid = threadIdx.x, wid = tid >> 5, lane = tid & 31;
    const int pb = blockIdx.x, b = blockIdx.y;
    const int p0 = pb * 128;

    float acc[16][4];
#pragma unroll
    for (int i = 0; i < 16; i++)
#pragma unroll
        for (int j = 0; j < 4; j++) acc[i][j] = 0.f;

    const int mwarp = (wid >> 2) * 64, nwarp = (wid & 3) * 32;

    gemm2(smb,
          g_oh + ((size_t)b * HW + p0) * INNER,
          g_wh + 3 * 16384, g_wl + 3 * 16384,
          false, tid, lane, mwarp, nwarp, acc);

    const int gid = lane >> 2, tig = lane & 3;
#pragma unroll
    for (int mt = 0; mt < 4; mt++) {
#pragma unroll
        for (int half = 0; half < 2; half++) {
            int c = mwarp + mt * 16 + gid + half * 8;
            float* dst = outp + ((size_t)b * C + c) * HW + p0;
#pragma unroll
            for (int nt = 0; nt < 4; nt++) {
                int col = nwarp + nt * 8 + 2 * tig;
                *(float2*)(dst + col) = make_float2(acc[mt * 4 + nt][half * 2],
                                                    acc[mt * 4 + nt][half * 2 + 1]);
            }
        }
    }
}

extern "C" void kernel_launch(void* const* d_in, const int* in_sizes, int n_in,
                              void* d_out, int out_size)
{
    const float* x     = (const float*)d_in[0];
    const float* wq    = (const float*)d_in[1];
    const float* wk    = (const float*)d_in[2];
    const float* wv    = (const float*)d_in[3];
    const float* wproj = (const float*)d_in[4];
    float* outp = (float*)d_out;

    cudaFuncSetAttribute(attn_kernel,
                         cudaFuncAttributeMaxDynamicSharedMemorySize, ATTN_SMEM);
    cudaFuncSetAttribute(qkv_mma_kernel,
                         cudaFuncAttributeMaxDynamicSharedMemorySize, GEMM_SMEM);
    cudaFuncSetAttribute(proj_mma_kernel,
                         cudaFuncAttributeMaxDynamicSharedMemorySize, GEMM_SMEM);

    xsplit_kernel<<<dim3(HW / 32, C / 32, 3), 256>>>(x, wq, wk, wv, wproj);
    qkv_mma_kernel<<<dim3(NTILES, 3, BATCH), 256, GEMM_SMEM>>>();
    attn_kernel<<<dim3(W / TX, H / TY, HEADS * BATCH), 256, ATTN_SMEM>>>();
    proj_mma_kernel<<<dim3(NTILES, BATCH), 256, GEMM_SMEM>>>(outp);
}

// round 14
// speedup vs baseline: 1.5479x; 1.0068x over previous
#include <cuda_runtime.h>
#include <cuda_fp16.h>
#include <cstdint>

#define BATCH 2
#define C 128
#define H 96
#define W 96
#define HEADS 4
#define DHEAD 32
#define PAD 2
#define INNER 128
#define HW (H * W)
#define HP (H + 2 * PAD)
#define WP (W + 2 * PAD)
#define NTILES (HW / 128)   // 72

typedef unsigned long long u64;

// fp32 scratch
__device__ float g_q[(size_t)BATCH * HW * INNER];            // [b][p][inner]
// plane-major k/v: [b][h][g(8)][yp][xp] float4 (padding stays zero)
__device__ float4 g_kpad4[(size_t)BATCH * HEADS * 8 * HP * WP];
__device__ float4 g_vpad4[(size_t)BATCH * HEADS * 8 * HP * WP];

// fp16 operand images, PRE-SWIZZLED: half (row, c) at row*128 + ((c>>3)^(row&7))*8 + (c&7)
__device__ __half g_xh[(size_t)BATCH * HW * C];              // rows = pixels
__device__ __half g_wh[4 * C * INNER];                       // rows = out-ch
__device__ __half g_wl[4 * C * INNER];
__device__ __half g_oh[(size_t)BATCH * HW * INNER];          // rows = pixels

#define FFMA2(d, a, b) \
    asm("fma.rn.f32x2 %0, %1, %2, %0;" : "+l"(d) : "l"(a), "l"(b))
#define PACK2(d, s) \
    asm("mov.b64 %0, {%1, %1};" : "=l"(d) : "f"(s))

__device__ __forceinline__ uint32_t smem_u32(const void* p) {
    uint32_t a;
    asm("{ .reg .u64 t; cvta.to.shared.u64 t, %1; cvt.u32.u64 %0, t; }"
        : "=r"(a) : "l"(p));
    return a;
}

#define MBARRIER_INIT(mb, n) \
    asm volatile("mbarrier.init.shared.b64 [%0], %1;" :: "r"((uint32_t)(mb)), "r"((uint32_t)(n)) : "memory")
#define MBARRIER_EXPECT_TX(mb, bytes) \
    asm volatile("mbarrier.arrive.expect_tx.shared.b64 _, [%0], %1;" \
                 :: "r"((uint32_t)(mb)), "r"((uint32_t)(bytes)) : "memory")
#define MBARRIER_WAIT_PARITY(mb, ph) do {                                         \
    uint32_t _mb = (uint32_t)(mb); uint32_t _ph = (uint32_t)(ph); uint32_t _done; \
    asm volatile("{ .reg .pred p; mbarrier.try_wait.parity.acquire.cta.shared::cta.b64 p, [%1], %2; selp.b32 %0, 1, 0, p; }" \
                 : "=r"(_done) : "r"(_mb), "r"(_ph) : "memory");                  \
    if (!_done) {                                                                 \
        asm volatile("{ .reg .pred P1; WL_%=: mbarrier.try_wait.parity.acquire.cta.shared::cta.b64 P1, [%0], %1, 0x989680; @P1 bra.uni WD_%=; bra.uni WL_%=; WD_%=: }" \
                     :: "r"(_mb), "r"(_ph) : "memory");                           \
    } } while (0)

#define BULK_G2S(dst, src, bytes, mbar) \
    asm volatile("cp.async.bulk.shared::cluster.global.mbarrier::complete_tx::bytes [%0], [%1], %2, [%3];" \
        :: "r"((uint32_t)(dst)), "l"(src), "r"((uint32_t)(bytes)), "r"((uint32_t)(mbar)) : "memory")

// pack two f32 -> f16x2 reg, v0 in low half (memory element 0)
#define PACK_F16X2(res, v0, v1) \
    asm("cvt.rn.f16x2.f32 %0, %1, %2;" : "=r"(res) : "f"(v1), "f"(v0))

#define LDM_X4(r, addr) \
    asm volatile("ldmatrix.sync.aligned.m8n8.x4.shared.b16 {%0,%1,%2,%3}, [%4];" \
        : "=r"((r)[0]), "=r"((r)[1]), "=r"((r)[2]), "=r"((r)[3]) : "r"(addr))

#define MMA16816(d, a, bp) \
    asm volatile("mma.sync.aligned.m16n8k16.row.col.f32.f16.f16.f32 " \
        "{%0,%1,%2,%3}, {%4,%5,%6,%7}, {%8,%9}, {%0,%1,%2,%3};" \
        : "+f"((d)[0]), "+f"((d)[1]), "+f"((d)[2]), "+f"((d)[3]) \
        : "r"((a)[0]), "r"((a)[1]), "r"((a)[2]), "r"((a)[3]), \
          "r"((bp)[0]), "r"((bp)[1]))

// GEMM smem: 3 dense 32KB tiles (256B rows, XOR-swizzled images) + 2 mbarriers
#define TILE 32768
#define GEMM_SMEM (3 * TILE + 32)

// swizzled half-index within a row: chunk (c>>3) ^ (row&7), sub c&7
__device__ __forceinline__ int sw_idx(int row, int c) {
    return (((c >> 3) ^ (row & 7)) << 3) + (c & 7);
}

// ---------------------------------------------------------------------------
// Kernel A: z<2: split x -> g_xh (fp16 [p][c], swizzled); z==2: bake weights
// ---------------------------------------------------------------------------
__global__ __launch_bounds__(256) void xsplit_kernel(
    const float* __restrict__ x,  const float* __restrict__ wq,
    const float* __restrict__ wk, const float* __restrict__ wv,
    const float* __restrict__ wp)
{
    if (blockIdx.z == 2) {
        int idx = (blockIdx.y * gridDim.x + blockIdx.x) * 256 + threadIdx.x;
        if (idx < 4 * C * INNER) {
            int mat = idx >> 14, e = idx & 16383;
            const float* __restrict__ src =
                (mat == 0) ? wq : (mat == 1) ? wk : (mat == 2) ? wv : wp;
            float w = src[e];
            int o = e >> 7, c = e & 127;
            __half hb = __float2half_rn(w);
            size_t off = (size_t)mat * 16384 + o * 128 + sw_idx(o, c);
            g_wh[off] = hb;
            g_wl[off] = __float2half_rn(w - __half2float(hb));
        }
        return;
    }
    __shared__ float t[32][33];
    const int p0 = blockIdx.x * 32, c0 = blockIdx.y * 32, b = blockIdx.z;
    const int tl = threadIdx.x & 31, th = threadIdx.x >> 5;
#pragma unroll
    for (int i = 0; i < 4; i++) {
        int c = th + i * 8;
        t[c][tl] = x[((size_t)b * C + c0 + c) * HW + p0 + tl];
    }
    __syncthreads();
#pragma unroll
    for (int i = 0; i < 4; i++) {
        int p = th + i * 8;
        int P = p0 + p, c = c0 + tl;
        g_xh[((size_t)b * HW + P) * C + sw_idx(P, c)] = __float2half_rn(t[tl][p]);
    }
}

// ---------------------------------------------------------------------------
// HMMA mainloop on dense 256B-row tiles with XOR swizzle
// ---------------------------------------------------------------------------
__device__ __forceinline__ void mma_tiles(
    uint32_t Abase, uint32_t Bbase, int lane, int mwarp, int nwarp,
    float (*acc)[4])
{
    const int xr = lane & 7;
    const uint32_t arowb = Abase + (uint32_t)(mwarp + (lane & 15)) * 256;
    const int ac0 = (lane >> 4) & 1;
    const uint32_t browb = Bbase
                         + (uint32_t)(nwarp + ((lane >> 4) << 3) + (lane & 7)) * 256;
    const int bc0 = (lane >> 3) & 1;
#pragma unroll
    for (int k0 = 0; k0 < 8; k0++) {
        const uint32_t aoff = (uint32_t)(((k0 * 2 + ac0) ^ xr) << 4);
        const uint32_t boff = (uint32_t)(((k0 * 2 + bc0) ^ xr) << 4);
        uint32_t a[4][4], bq[2][4];
#pragma unroll
        for (int mt = 0; mt < 4; mt++)
            LDM_X4(a[mt], arowb + mt * (16 * 256) + aoff);
#pragma unroll
        for (int n2 = 0; n2 < 2; n2++)
            LDM_X4(bq[n2], browb + n2 * (16 * 256) + boff);
#pragma unroll
        for (int mt = 0; mt < 4; mt++)
#pragma unroll
            for (int nt = 0; nt < 4; nt++)
                MMA16816(acc[mt * 4 + nt], a[mt], &bq[nt >> 1][(nt & 1) * 2]);
    }
}

// 2-pass GEMM with bulk staging: S0=comm, S1=o1, S2=o2
__device__ __forceinline__ void gemm2(
    uint32_t smb,
    const __half* __restrict__ comm, const __half* __restrict__ o1,
    const __half* __restrict__ o2, bool comm_is_A,
    int tid, int lane, int mwarp, int nwarp, float (*acc)[4])
{
    const uint32_t S0 = smb, S1 = smb + TILE, S2 = smb + 2 * TILE;
    const uint32_t MB0 = smb + 3 * TILE, MB1 = MB0 + 8;

    if (tid == 0) { MBARRIER_INIT(MB0, 2); MBARRIER_INIT(MB1, 1); }
    __syncthreads();
    if (tid == 0)       { MBARRIER_EXPECT_TX(MB0, TILE); BULK_G2S(S0, comm, TILE, MB0); }
    else if (tid == 32) { MBARRIER_EXPECT_TX(MB0, TILE); BULK_G2S(S1, o1, TILE, MB0); }
    else if (tid == 64) { MBARRIER_EXPECT_TX(MB1, TILE); BULK_G2S(S2, o2, TILE, MB1); }

    MBARRIER_WAIT_PARITY(MB0, 0);
    if (comm_is_A) mma_tiles(S0, S1, lane, mwarp, nwarp, acc);
    else           mma_tiles(S1, S0, lane, mwarp, nwarp, acc);
    MBARRIER_WAIT_PARITY(MB1, 0);
    if (comm_is_A) mma_tiles(S0, S2, lane, mwarp, nwarp, acc);
    else           mma_tiles(S2, S0, lane, mwarp, nwarp, acc);
}

// ---------------------------------------------------------------------------
// Kernel 1: QKV. D[p][o] = Xh[p][c] * (Wh + Wl)[o][c].
// k/v outputs go to plane-major g_kpad4/g_vpad4.
// ---------------------------------------------------------------------------
__global__ __launch_bounds__(256, 2) void qkv_mma_kernel()
{
    extern __shared__ char sm[];
    const uint32_t smb = smem_u32(sm);
    const int tid = threadIdx.x, wid = tid >> 5, lane = tid & 31;
    const int pb = blockIdx.x, mat = blockIdx.y, b = blockIdx.z;
    const int p0 = pb * 128;

    float acc[16][4];
#pragma unroll
    for (int i = 0; i < 16; i++)
#pragma unroll
        for (int j = 0; j < 4; j++) acc[i][j] = 0.f;

    const int mwarp = (wid >> 2) * 64, nwarp = (wid & 3) * 32;

    gemm2(smb,
          g_xh + ((size_t)b * HW + p0) * C,
          g_wh + mat * 16384, g_wl + mat * 16384,
          true, tid, lane, mwarp, nwarp, acc);

    const int gid = lane >> 2, tig = lane & 3;
#pragma unroll
    for (int mt = 0; mt < 4; mt++) {
#pragma unroll
        for (int half = 0; half < 2; half++) {
            int r = mwarp + mt * 16 + gid + half * 8;
            int p = p0 + r;
            if (mat == 0) {
                float* dst = g_q + ((size_t)b * HW + p) * INNER;
#pragma unroll
                for (int nt = 0; nt < 4; nt++) {
                    int o = nwarp + nt * 8 + 2 * tig;
                    *(float2*)(dst + o) = make_float2(acc[mt * 4 + nt][half * 2],
                                                      acc[mt * 4 + nt][half * 2 + 1]);
                }
            } else {
                int yy = p / W, xx = p - yy * W;
                float4* base = (mat == 1) ? g_kpad4 : g_vpad4;
#pragma unroll
                for (int nt = 0; nt < 4; nt++) {
                    int c = nwarp + nt * 8 + 2 * tig;
                    int h = c >> 5, g = (c >> 2) & 7, sub = c & 3;
                    float* dst = (float*)(base
                        + ((((size_t)(b * HEADS + h) * 8 + g) * HP + yy + PAD) * WP
                           + xx + PAD)) + sub;
                    *(float2*)dst = make_float2(acc[mt * 4 + nt][half * 2],
                                                acc[mt * 4 + nt][half * 2 + 1]);
                }
            }
        }
    }
}

// ---------------------------------------------------------------------------
// Kernel 2: window attention (fused one-pass), bulk-staged halo.
// ---------------------------------------------------------------------------
#define TX 32
#define TY 8
#define PWT (TX + 4)     // 36
#define PHT (TY + 4)     // 12
#define DGS 433
#define ATTN_SMEM (2 * 8 * DGS * 16 + 16)   // + mbarrier

__global__ __launch_bounds__(256, 2) void attn_kernel()
{
    extern __shared__ float4 sm4[];
    float4* ks4 = sm4;
    float4* vs4 = sm4 + 8 * DGS;
    const uint32_t smbk = smem_u32(ks4);
    const uint32_t smbv = smem_u32(vs4);
    const uint32_t MB = smbk + 2 * 8 * DGS * 16;

    const int t  = threadIdx.x;
    const int x0 = blockIdx.x * TX;
    const int y0 = blockIdx.y * TY;
    const int h  = blockIdx.z & 3;
    const int b  = blockIdx.z >> 2;

    if (t == 0) MBARRIER_INIT(MB, 192);
    __syncthreads();

    // 192 bulk copies: 2(kv) x 8 planes x 12 rows, 576B each
    if (t < 192) {
        int kv = t >= 96;
        int j  = t - kv * 96;
        int pl = j / 12, py = j - pl * 12;
        int gsrc = (pl & 1) * 4 + (pl >> 1);
        const float4* src = (kv ? g_vpad4 : g_kpad4)
            + (((size_t)(b * HEADS + h) * 8 + gsrc) * HP + y0 + py) * WP + x0;
        uint32_t dst = (kv ? smbv : smbk) + (uint32_t)(pl * DGS + py * PWT) * 16;
        MBARRIER_EXPECT_TX(MB, 576);
        BULK_G2S(dst, src, 576, MB);
    }

    const int hh   = t & 1;          // d-half
    const int pair = t >> 1;         // 0..127
    const int tx2  = pair & 15;
    const int ty   = pair >> 4;
    const int p0p  = (y0 + ty) * W + x0 + 2 * tx2;

    const float scale = 0.17677669529663687f;  // 1/sqrt(32)
    float q0f[16], q1f[16];
    {
        const float* qp0 = g_q + ((size_t)b * HW + p0p) * INNER + h * DHEAD + hh * 16;
        const float* qp1 = qp0 + INNER;
#pragma unroll
        for (int i = 0; i < 4; i++) {
            float4 v0 = *(const float4*)(qp0 + i * 4);
            float4 v1 = *(const float4*)(qp1 + i * 4);
            q0f[4 * i] = v0.x * scale; q0f[4 * i + 1] = v0.y * scale;
            q0f[4 * i + 2] = v0.z * scale; q0f[4 * i + 3] = v0.w * scale;
            q1f[4 * i] = v1.x * scale; q1f[4 * i + 1] = v1.y * scale;
            q1f[4 * i + 2] = v1.z * scale; q1f[4 * i + 3] = v1.w * scale;
        }
    }
    u64 q0[8], q1[8];
#pragma unroll
    for (int i = 0; i < 8; i++) {
        q0[i] = *(u64*)&q0f[2 * i];
        q1[i] = *(u64*)&q1f[2 * i];
    }

    MBARRIER_WAIT_PARITY(MB, 0);
    __syncthreads();

    u64 o0[8], o1[8];
#pragma unroll
    for (int i = 0; i < 8; i++) { o0[i] = 0ull; o1[i] = 0ull; }
    float sum0 = 0.f, sum1 = 0.f;

#pragma unroll
    for (int di = 0; di < 5; di++) {
#pragma unroll
        for (int djj = 0; djj < 6; djj++) {
            const int pixi = (ty + di) * PWT + 2 * tx2 + djj;

            u64 a0 = 0ull, a1 = 0ull, b0 = 0ull, b1 = 0ull;
#pragma unroll
            for (int dgl = 0; dgl < 4; dgl++) {
                ulonglong2 kq = *(const ulonglong2*)&ks4[(dgl * 2 + hh) * DGS + pixi];
                FFMA2(a0, q0[2 * dgl], kq.x);
                FFMA2(a1, q0[2 * dgl + 1], kq.y);
                FFMA2(b0, q1[2 * dgl], kq.x);
                FFMA2(b1, q1[2 * dgl + 1], kq.y);
            }
            float2 fa0 = *(float2*)&a0, fa1 = *(float2*)&a1;
            float2 fb0 = *(float2*)&b0, fb1 = *(float2*)&b1;
            float p0s = (fa0.x + fa0.y) + (fa1.x + fa1.y);
            float p1s = (fb0.x + fb0.y) + (fb1.x + fb1.y);
            p0s += __shfl_xor_sync(0xffffffffu, p0s, 1);
            p1s += __shfl_xor_sync(0xffffffffu, p1s, 1);

            u64 w0 = 0ull, w1 = 0ull;
            if (djj < 5) {
                float e = __expf(p0s);
                sum0 += e;
                PACK2(w0, e);
            }
            if (djj > 0) {
                float e = __expf(p1s);
                sum1 += e;
                PACK2(w1, e);
            }

#pragma unroll
            for (int dgl = 0; dgl < 4; dgl++) {
                ulonglong2 vq = *(const ulonglong2*)&vs4[(dgl * 2 + hh) * DGS + pixi];
                if (djj < 5) {
                    FFMA2(o0[2 * dgl], w0, vq.x);
                    FFMA2(o0[2 * dgl + 1], w0, vq.y);
                }
                if (djj > 0) {
                    FFMA2(o1[2 * dgl], w1, vq.x);
                    FFMA2(o1[2 * dgl + 1], w1, vq.y);
                }
            }
        }
    }

    const float inv0 = 1.f / sum0, inv1 = 1.f / sum1;

    // store fp16, swizzled image: chunks (h*4+hh*2+{0,1}) ^ (P&7)
#pragma unroll
    for (int px = 0; px < 2; px++) {
        const u64* oo = px ? o1 : o0;
        const float inv = px ? inv1 : inv0;
        uint32_t hu[8];
#pragma unroll
        for (int i = 0; i < 8; i++) {
            float2 f = *(float2*)&oo[i];
            PACK_F16X2(hu[i], f.x * inv, f.y * inv);
        }
        const int P = p0p + px;
        __half* rowp = g_oh + ((size_t)b * HW + P) * INNER;
        const int cb = h * 4 + hh * 2, xr = P & 7;
        *(uint4*)(rowp + ((cb ^ xr) << 3))       = make_uint4(hu[0], hu[1], hu[2], hu[3]);
        *(uint4*)(rowp + (((cb + 1) ^ xr) << 3)) = make_uint4(hu[4], hu[5], hu[6], hu[7]);
    }
}

// ---------------------------------------------------------------------------
// Kernel 3: proj. D[c][p] = (Wph + Wpl)[c][i] * Oh[p][i]. -> NCHW.
// ---------------------------------------------------------------------------
__global__ __launch_bounds__(256, 2) void proj_mma_kernel(float* __restrict__ outp)
{
    extern __shared__ char sm[];
    const uint32_t smb = smem_u32(sm);
    const int tid = threadIdx.x, wid = tid >> 5, lane = tid & 31;
    const int pb = blockIdx.x, b = blockIdx.y;
    const int p0 = pb * 128;

    float acc[16][4];
#pragma unroll
    for (int i = 0; i < 16; i++)
#pragma unroll
        for (int j = 0; j < 4; j++) acc[i][j] = 0.f;

    const int mwarp = (wid >> 2) * 64, nwarp = (wid & 3) * 32;

    gemm2(smb,
          g_oh + ((size_t)b * HW + p0) * INNER,
          g_wh + 3 * 16384, g_wl + 3 * 16384,
          false, tid, lane, mwarp, nwarp, acc);

    const int gid = lane >> 2, tig = lane & 3;
#pragma unroll
    for (int mt = 0; mt < 4; mt++) {
#pragma unroll
        for (int half = 0; half < 2; half++) {
            int c = mwarp + mt * 16 + gid + half * 8;
            float* dst = outp + ((size_t)b * C + c) * HW + p0;
#pragma unroll
            for (int nt = 0; nt < 4; nt++) {
                int col = nwarp + nt * 8 + 2 * tig;
                *(float2*)(dst + col) = make_float2(acc[mt * 4 + nt][half * 2],
                                                    acc[mt * 4 + nt][half * 2 + 1]);
            }
        }
    }
}

extern "C" void kernel_launch(void* const* d_in, const int* in_sizes, int n_in,
                              void* d_out, int out_size)
{
    const float* x     = (const float*)d_in[0];
    const float* wq    = (const float*)d_in[1];
    const float* wk    = (const float*)d_in[2];
    const float* wv    = (const float*)d_in[3];
    const float* wproj = (const float*)d_in[4];
    float* outp = (float*)d_out;

    cudaFuncSetAttribute(attn_kernel,
                         cudaFuncAttributeMaxDynamicSharedMemorySize, ATTN_SMEM);
    cudaFuncSetAttribute(qkv_mma_kernel,
                         cudaFuncAttributeMaxDynamicSharedMemorySize, GEMM_SMEM);
    cudaFuncSetAttribute(proj_mma_kernel,
                         cudaFuncAttributeMaxDynamicSharedMemorySize, GEMM_SMEM);

    xsplit_kernel<<<dim3(HW / 32, C / 32, 3), 256>>>(x, wq, wk, wv, wproj);
    qkv_mma_kernel<<<dim3(NTILES, 3, BATCH), 256, GEMM_SMEM>>>();
    attn_kernel<<<dim3(W / TX, H / TY, HEADS * BATCH), 256, ATTN_SMEM>>>();
    proj_mma_kernel<<<dim3(NTILES, BATCH), 256, GEMM_SMEM>>>(outp);
}

// round 15
// speedup vs baseline: 1.5493x; 1.0009x over previous
#include <cuda_runtime.h>
#include <cuda_fp16.h>
#include <cstdint>

#define BATCH 2
#define C 128
#define H 96
#define W 96
#define HEADS 4
#define DHEAD 32
#define PAD 2
#define INNER 128
#define HW (H * W)
#define HP (H + 2 * PAD)
#define WP (W + 2 * PAD)
#define NTILES (HW / 128)   // 72

typedef unsigned long long u64;

// fp32 scratch
__device__ float g_q[(size_t)BATCH * HW * INNER];            // [b][p][inner]
// plane-major k/v: [b][h][g(8)][yp][xp] float4 (padding stays zero)
__device__ float4 g_kpad4[(size_t)BATCH * HEADS * 8 * HP * WP];
__device__ float4 g_vpad4[(size_t)BATCH * HEADS * 8 * HP * WP];

// fp16 operand images, PRE-SWIZZLED: half (row, c) at row*128 + ((c>>3)^(row&7))*8 + (c&7)
__device__ __half g_xh[(size_t)BATCH * HW * C];              // rows = pixels
__device__ __half g_wh[4 * C * INNER];                       // rows = out-ch
__device__ __half g_wl[4 * C * INNER];
__device__ __half g_oh[(size_t)BATCH * HW * INNER];          // rows = pixels

#define FFMA2(d, a, b) \
    asm("fma.rn.f32x2 %0, %1, %2, %0;" : "+l"(d) : "l"(a), "l"(b))
#define PACK2(d, s) \
    asm("mov.b64 %0, {%1, %1};" : "=l"(d) : "f"(s))

__device__ __forceinline__ uint32_t smem_u32(const void* p) {
    uint32_t a;
    asm("{ .reg .u64 t; cvta.to.shared.u64 t, %1; cvt.u32.u64 %0, t; }"
        : "=r"(a) : "l"(p));
    return a;
}

#define MBARRIER_INIT(mb, n) \
    asm volatile("mbarrier.init.shared.b64 [%0], %1;" :: "r"((uint32_t)(mb)), "r"((uint32_t)(n)) : "memory")
#define MBARRIER_EXPECT_TX(mb, bytes) \
    asm volatile("mbarrier.arrive.expect_tx.shared.b64 _, [%0], %1;" \
                 :: "r"((uint32_t)(mb)), "r"((uint32_t)(bytes)) : "memory")
#define MBARRIER_WAIT_PARITY(mb, ph) do {                                         \
    uint32_t _mb = (uint32_t)(mb); uint32_t _ph = (uint32_t)(ph); uint32_t _done; \
    asm volatile("{ .reg .pred p; mbarrier.try_wait.parity.acquire.cta.shared::cta.b64 p, [%1], %2; selp.b32 %0, 1, 0, p; }" \
                 : "=r"(_done) : "r"(_mb), "r"(_ph) : "memory");                  \
    if (!_done) {                                                                 \
        asm volatile("{ .reg .pred P1; WL_%=: mbarrier.try_wait.parity.acquire.cta.shared::cta.b64 P1, [%0], %1, 0x989680; @P1 bra.uni WD_%=; bra.uni WL_%=; WD_%=: }" \
                     :: "r"(_mb), "r"(_ph) : "memory");                           \
    } } while (0)

#define BULK_G2S(dst, src, bytes, mbar) \
    asm volatile("cp.async.bulk.shared::cluster.global.mbarrier::complete_tx::bytes [%0], [%1], %2, [%3];" \
        :: "r"((uint32_t)(dst)), "l"(src), "r"((uint32_t)(bytes)), "r"((uint32_t)(mbar)) : "memory")

// pack two f32 -> f16x2 reg, v0 in low half (memory element 0)
#define PACK_F16X2(res, v0, v1) \
    asm("cvt.rn.f16x2.f32 %0, %1, %2;" : "=r"(res) : "f"(v1), "f"(v0))

#define LDM_X4(r, addr) \
    asm volatile("ldmatrix.sync.aligned.m8n8.x4.shared.b16 {%0,%1,%2,%3}, [%4];" \
        : "=r"((r)[0]), "=r"((r)[1]), "=r"((r)[2]), "=r"((r)[3]) : "r"(addr))

#define MMA16816(d, a, bp) \
    asm volatile("mma.sync.aligned.m16n8k16.row.col.f32.f16.f16.f32 " \
        "{%0,%1,%2,%3}, {%4,%5,%6,%7}, {%8,%9}, {%0,%1,%2,%3};" \
        : "+f"((d)[0]), "+f"((d)[1]), "+f"((d)[2]), "+f"((d)[3]) \
        : "r"((a)[0]), "r"((a)[1]), "r"((a)[2]), "r"((a)[3]), \
          "r"((bp)[0]), "r"((bp)[1]))

// GEMM smem: dense 32KB tiles (256B rows, XOR-swizzled images) + mbarriers
#define TILE 32768
#define HTILE 16384
#define GEMM_SMEM (3 * TILE + 32)           // qkv: 3 full tiles
#define PROJ_SMEM (HTILE + 2 * TILE + 32)   // proj: 16K B-tile + 2 W tiles

// swizzled half-index within a row: chunk (c>>3) ^ (row&7), sub c&7
__device__ __forceinline__ int sw_idx(int row, int c) {
    return (((c >> 3) ^ (row & 7)) << 3) + (c & 7);
}

// ---------------------------------------------------------------------------
// Kernel A: z<2: split x -> g_xh (fp16 [p][c], swizzled); z==2: bake weights
// ---------------------------------------------------------------------------
__global__ __launch_bounds__(256) void xsplit_kernel(
    const float* __restrict__ x,  const float* __restrict__ wq,
    const float* __restrict__ wk, const float* __restrict__ wv,
    const float* __restrict__ wp)
{
    if (blockIdx.z == 2) {
        int idx = (blockIdx.y * gridDim.x + blockIdx.x) * 256 + threadIdx.x;
        if (idx < 4 * C * INNER) {
            int mat = idx >> 14, e = idx & 16383;
            const float* __restrict__ src =
                (mat == 0) ? wq : (mat == 1) ? wk : (mat == 2) ? wv : wp;
            float w = src[e];
            int o = e >> 7, c = e & 127;
            __half hb = __float2half_rn(w);
            size_t off = (size_t)mat * 16384 + o * 128 + sw_idx(o, c);
            g_wh[off] = hb;
            g_wl[off] = __float2half_rn(w - __half2float(hb));
        }
        return;
    }
    __shared__ float t[32][33];
    const int p0 = blockIdx.x * 32, c0 = blockIdx.y * 32, b = blockIdx.z;
    const int tl = threadIdx.x & 31, th = threadIdx.x >> 5;
#pragma unroll
    for (int i = 0; i < 4; i++) {
        int c = th + i * 8;
        t[c][tl] = x[((size_t)b * C + c0 + c) * HW + p0 + tl];
    }
    __syncthreads();
#pragma unroll
    for (int i = 0; i < 4; i++) {
        int p = th + i * 8;
        int P = p0 + p, c = c0 + tl;
        g_xh[((size_t)b * HW + P) * C + sw_idx(P, c)] = __float2half_rn(t[tl][p]);
    }
}

// ---------------------------------------------------------------------------
// HMMA mainloop on dense 256B-row tiles with XOR swizzle (full 128x128)
// ---------------------------------------------------------------------------
__device__ __forceinline__ void mma_tiles(
    uint32_t Abase, uint32_t Bbase, int lane, int mwarp, int nwarp,
    float (*acc)[4])
{
    const int xr = lane & 7;
    const uint32_t arowb = Abase + (uint32_t)(mwarp + (lane & 15)) * 256;
    const int ac0 = (lane >> 4) & 1;
    const uint32_t browb = Bbase
                         + (uint32_t)(nwarp + ((lane >> 4) << 3) + (lane & 7)) * 256;
    const int bc0 = (lane >> 3) & 1;
#pragma unroll
    for (int k0 = 0; k0 < 8; k0++) {
        const uint32_t aoff = (uint32_t)(((k0 * 2 + ac0) ^ xr) << 4);
        const uint32_t boff = (uint32_t)(((k0 * 2 + bc0) ^ xr) << 4);
        uint32_t a[4][4], bq[2][4];
#pragma unroll
        for (int mt = 0; mt < 4; mt++)
            LDM_X4(a[mt], arowb + mt * (16 * 256) + aoff);
#pragma unroll
        for (int n2 = 0; n2 < 2; n2++)
            LDM_X4(bq[n2], browb + n2 * (16 * 256) + boff);
#pragma unroll
        for (int mt = 0; mt < 4; mt++)
#pragma unroll
            for (int nt = 0; nt < 4; nt++)
                MMA16816(acc[mt * 4 + nt], a[mt], &bq[nt >> 1][(nt & 1) * 2]);
    }
}

// Variant for 64-row B tile: warp covers 16 B-rows (one ldmatrix x4 per k0)
__device__ __forceinline__ void mma_tiles_n64(
    uint32_t Abase, uint32_t Bbase, int lane, int mwarp, int nwarp,
    float (*acc)[4])
{
    const int xr = lane & 7;
    const uint32_t arowb = Abase + (uint32_t)(mwarp + (lane & 15)) * 256;
    const int ac0 = (lane >> 4) & 1;
    const uint32_t browb = Bbase
                         + (uint32_t)(nwarp + ((lane >> 4) << 3) + (lane & 7)) * 256;
    const int bc0 = (lane >> 3) & 1;
#pragma unroll
    for (int k0 = 0; k0 < 8; k0++) {
        const uint32_t aoff = (uint32_t)(((k0 * 2 + ac0) ^ xr) << 4);
        const uint32_t boff = (uint32_t)(((k0 * 2 + bc0) ^ xr) << 4);
        uint32_t a[4][4], bq[4];
#pragma unroll
        for (int mt = 0; mt < 4; mt++)
            LDM_X4(a[mt], arowb + mt * (16 * 256) + aoff);
        LDM_X4(bq, browb + boff);
#pragma unroll
        for (int mt = 0; mt < 4; mt++)
#pragma unroll
            for (int nt = 0; nt < 2; nt++)
                MMA16816(acc[mt * 2 + nt], a[mt], &bq[nt * 2]);
    }
}

// 2-pass GEMM with bulk staging: S0=comm, S1=o1, S2=o2 (all 32KB; qkv path)
__device__ __forceinline__ void gemm2(
    uint32_t smb,
    const __half* __restrict__ comm, const __half* __restrict__ o1,
    const __half* __restrict__ o2,
    int tid, int lane, int mwarp, int nwarp, float (*acc)[4])
{
    const uint32_t S0 = smb, S1 = smb + TILE, S2 = smb + 2 * TILE;
    const uint32_t MB0 = smb + 3 * TILE, MB1 = MB0 + 8;

    if (tid == 0) { MBARRIER_INIT(MB0, 2); MBARRIER_INIT(MB1, 1); }
    __syncthreads();
    if (tid == 0)       { MBARRIER_EXPECT_TX(MB0, TILE); BULK_G2S(S0, comm, TILE, MB0); }
    else if (tid == 32) { MBARRIER_EXPECT_TX(MB0, TILE); BULK_G2S(S1, o1, TILE, MB0); }
    else if (tid == 64) { MBARRIER_EXPECT_TX(MB1, TILE); BULK_G2S(S2, o2, TILE, MB1); }

    MBARRIER_WAIT_PARITY(MB0, 0);
    mma_tiles(S0, S1, lane, mwarp, nwarp, acc);
    MBARRIER_WAIT_PARITY(MB1, 0);
    mma_tiles(S0, S2, lane, mwarp, nwarp, acc);
}

// ---------------------------------------------------------------------------
// Kernel 1: QKV. D[p][o] = Xh[p][c] * (Wh + Wl)[o][c].
// ---------------------------------------------------------------------------
__global__ __launch_bounds__(256, 2) void qkv_mma_kernel()
{
    extern __shared__ char sm[];
    const uint32_t smb = smem_u32(sm);
    const int tid = threadIdx.x, wid = tid >> 5, lane = tid & 31;
    const int pb = blockIdx.x, mat = blockIdx.y, b = blockIdx.z;
    const int p0 = pb * 128;

    float acc[16][4];
#pragma unroll
    for (int i = 0; i < 16; i++)
#pragma unroll
        for (int j = 0; j < 4; j++) acc[i][j] = 0.f;

    const int mwarp = (wid >> 2) * 64, nwarp = (wid & 3) * 32;

    gemm2(smb,
          g_xh + ((size_t)b * HW + p0) * C,
          g_wh + mat * 16384, g_wl + mat * 16384,
          tid, lane, mwarp, nwarp, acc);

    const int gid = lane >> 2, tig = lane & 3;
#pragma unroll
    for (int mt = 0; mt < 4; mt++) {
#pragma unroll
        for (int half = 0; half < 2; half++) {
            int r = mwarp + mt * 16 + gid + half * 8;
            int p = p0 + r;
            if (mat == 0) {
                float* dst = g_q + ((size_t)b * HW + p) * INNER;
#pragma unroll
                for (int nt = 0; nt < 4; nt++) {
                    int o = nwarp + nt * 8 + 2 * tig;
                    *(float2*)(dst + o) = make_float2(acc[mt * 4 + nt][half * 2],
                                                      acc[mt * 4 + nt][half * 2 + 1]);
                }
            } else {
                int yy = p / W, xx = p - yy * W;
                float4* base = (mat == 1) ? g_kpad4 : g_vpad4;
#pragma unroll
                for (int nt = 0; nt < 4; nt++) {
                    int c = nwarp + nt * 8 + 2 * tig;
                    int h = c >> 5, g = (c >> 2) & 7, sub = c & 3;
                    float* dst = (float*)(base
                        + ((((size_t)(b * HEADS + h) * 8 + g) * HP + yy + PAD) * WP
                           + xx + PAD)) + sub;
                    *(float2*)dst = make_float2(acc[mt * 4 + nt][half * 2],
                                                acc[mt * 4 + nt][half * 2 + 1]);
                }
            }
        }
    }
}

// ---------------------------------------------------------------------------
// Kernel 2: window attention (fused one-pass), bulk-staged halo.
// ---------------------------------------------------------------------------
#define TX 32
#define TY 8
#define PWT (TX + 4)     // 36
#define PHT (TY + 4)     // 12
#define DGS 433
#define ATTN_SMEM (2 * 8 * DGS * 16 + 16)   // + mbarrier

__global__ __launch_bounds__(256, 2) void attn_kernel()
{
    extern __shared__ float4 sm4[];
    float4* ks4 = sm4;
    float4* vs4 = sm4 + 8 * DGS;
    const uint32_t smbk = smem_u32(ks4);
    const uint32_t smbv = smem_u32(vs4);
    const uint32_t MB = smbk + 2 * 8 * DGS * 16;

    const int t  = threadIdx.x;
    const int x0 = blockIdx.x * TX;
    const int y0 = blockIdx.y * TY;
    const int h  = blockIdx.z & 3;
    const int b  = blockIdx.z >> 2;

    if (t == 0) MBARRIER_INIT(MB, 192);
    __syncthreads();

    // 192 bulk copies: 2(kv) x 8 planes x 12 rows, 576B each
    if (t < 192) {
        int kv = t >= 96;
        int j  = t - kv * 96;
        int pl = j / 12, py = j - pl * 12;
        int gsrc = (pl & 1) * 4 + (pl >> 1);
        const float4* src = (kv ? g_vpad4 : g_kpad4)
            + (((size_t)(b * HEADS + h) * 8 + gsrc) * HP + y0 + py) * WP + x0;
        uint32_t dst = (kv ? smbv : smbk) + (uint32_t)(pl * DGS + py * PWT) * 16;
        MBARRIER_EXPECT_TX(MB, 576);
        BULK_G2S(dst, src, 576, MB);
    }

    const int hh   = t & 1;          // d-half
    const int pair = t >> 1;         // 0..127
    const int tx2  = pair & 15;
    const int ty   = pair >> 4;
    const int p0p  = (y0 + ty) * W + x0 + 2 * tx2;

    const float scale = 0.17677669529663687f;  // 1/sqrt(32)
    float q0f[16], q1f[16];
    {
        const float* qp0 = g_q + ((size_t)b * HW + p0p) * INNER + h * DHEAD + hh * 16;
        const float* qp1 = qp0 + INNER;
#pragma unroll
        for (int i = 0; i < 4; i++) {
            float4 v0 = *(const float4*)(qp0 + i * 4);
            float4 v1 = *(const float4*)(qp1 + i * 4);
            q0f[4 * i] = v0.x * scale; q0f[4 * i + 1] = v0.y * scale;
            q0f[4 * i + 2] = v0.z * scale; q0f[4 * i + 3] = v0.w * scale;
            q1f[4 * i] = v1.x * scale; q1f[4 * i + 1] = v1.y * scale;
            q1f[4 * i + 2] = v1.z * scale; q1f[4 * i + 3] = v1.w * scale;
        }
    }
    u64 q0[8], q1[8];
#pragma unroll
    for (int i = 0; i < 8; i++) {
        q0[i] = *(u64*)&q0f[2 * i];
        q1[i] = *(u64*)&q1f[2 * i];
    }

    MBARRIER_WAIT_PARITY(MB, 0);
    __syncthreads();

    u64 o0[8], o1[8];
#pragma unroll
    for (int i = 0; i < 8; i++) { o0[i] = 0ull; o1[i] = 0ull; }
    float sum0 = 0.f, sum1 = 0.f;

#pragma unroll
    for (int di = 0; di < 5; di++) {
#pragma unroll
        for (int djj = 0; djj < 6; djj++) {
            const int pixi = (ty + di) * PWT + 2 * tx2 + djj;

            u64 a0 = 0ull, a1 = 0ull, b0 = 0ull, b1 = 0ull;
#pragma unroll
            for (int dgl = 0; dgl < 4; dgl++) {
                ulonglong2 kq = *(const ulonglong2*)&ks4[(dgl * 2 + hh) * DGS + pixi];
                FFMA2(a0, q0[2 * dgl], kq.x);
                FFMA2(a1, q0[2 * dgl + 1], kq.y);
                FFMA2(b0, q1[2 * dgl], kq.x);
                FFMA2(b1, q1[2 * dgl + 1], kq.y);
            }
            float2 fa0 = *(float2*)&a0, fa1 = *(float2*)&a1;
            float2 fb0 = *(float2*)&b0, fb1 = *(float2*)&b1;
            float p0s = (fa0.x + fa0.y) + (fa1.x + fa1.y);
            float p1s = (fb0.x + fb0.y) + (fb1.x + fb1.y);
            p0s += __shfl_xor_sync(0xffffffffu, p0s, 1);
            p1s += __shfl_xor_sync(0xffffffffu, p1s, 1);

            u64 w0 = 0ull, w1 = 0ull;
            if (djj < 5) {
                float e = __expf(p0s);
                sum0 += e;
                PACK2(w0, e);
            }
            if (djj > 0) {
                float e = __expf(p1s);
                sum1 += e;
                PACK2(w1, e);
            }

#pragma unroll
            for (int dgl = 0; dgl < 4; dgl++) {
                ulonglong2 vq = *(const ulonglong2*)&vs4[(dgl * 2 + hh) * DGS + pixi];
                if (djj < 5) {
                    FFMA2(o0[2 * dgl], w0, vq.x);
                    FFMA2(o0[2 * dgl + 1], w0, vq.y);
                }
                if (djj > 0) {
                    FFMA2(o1[2 * dgl], w1, vq.x);
                    FFMA2(o1[2 * dgl + 1], w1, vq.y);
                }
            }
        }
    }

    const float inv0 = 1.f / sum0, inv1 = 1.f / sum1;

    // store fp16, swizzled image: chunks (h*4+hh*2+{0,1}) ^ (P&7)
#pragma unroll
    for (int px = 0; px < 2; px++) {
        const u64* oo = px ? o1 : o0;
        const float inv = px ? inv1 : inv0;
        uint32_t hu[8];
#pragma unroll
        for (int i = 0; i < 8; i++) {
            float2 f = *(float2*)&oo[i];
            PACK_F16X2(hu[i], f.x * inv, f.y * inv);
        }
        const int P = p0p + px;
        __half* rowp = g_oh + ((size_t)b * HW + P) * INNER;
        const int cb = h * 4 + hh * 2, xr = P & 7;
        *(uint4*)(rowp + ((cb ^ xr) << 3))       = make_uint4(hu[0], hu[1], hu[2], hu[3]);
        *(uint4*)(rowp + (((cb + 1) ^ xr) << 3)) = make_uint4(hu[4], hu[5], hu[6], hu[7]);
    }
}

// ---------------------------------------------------------------------------
// Kernel 3: proj, 64-pixel tiles. D[c][p] = (Wph + Wpl)[c][i] * Oh[p][i].
// grid (2*NTILES, BATCH), warp tile 64x16, acc 8x4.
// ---------------------------------------------------------------------------
__global__ __launch_bounds__(256, 2) void proj_mma_kernel(float* __restrict__ outp)
{
    extern __shared__ char sm[];
    const uint32_t smb = smem_u32(sm);
    const int tid = threadIdx.x, wid = tid >> 5, lane = tid & 31;
    const int pb = blockIdx.x, b = blockIdx.y;
    const int p0 = pb * 64;

    const uint32_t SB = smb;                    // Oh tile, 64 rows = 16KB
    const uint32_t S1 = smb + HTILE;            // Wh, 32KB
    const uint32_t S2 = smb + HTILE + TILE;     // Wl, 32KB
    const uint32_t MB0 = smb + HTILE + 2 * TILE, MB1 = MB0 + 8;

    if (tid == 0) { MBARRIER_INIT(MB0, 2); MBARRIER_INIT(MB1, 1); }
    __syncthreads();
    const __half* bh = g_oh + ((size_t)b * HW + p0) * INNER;
    if (tid == 0)       { MBARRIER_EXPECT_TX(MB0, HTILE); BULK_G2S(SB, bh, HTILE, MB0); }
    else if (tid == 32) { MBARRIER_EXPECT_TX(MB0, TILE); BULK_G2S(S1, g_wh + 3 * 16384, TILE, MB0); }
    else if (tid == 64) { MBARRIER_EXPECT_TX(MB1, TILE); BULK_G2S(S2, g_wl + 3 * 16384, TILE, MB1); }

    float acc[8][4];
#pragma unroll
    for (int i = 0; i < 8; i++)
#pragma unroll
        for (int j = 0; j < 4; j++) acc[i][j] = 0.f;

    const int mwarp = (wid >> 2) * 64, nwarp = (wid & 3) * 16;

    MBARRIER_WAIT_PARITY(MB0, 0);
    mma_tiles_n64(S1, SB, lane, mwarp, nwarp, acc);
    MBARRIER_WAIT_PARITY(MB1, 0);
    mma_tiles_n64(S2, SB, lane, mwarp, nwarp, acc);

    const int gid = lane >> 2, tig = lane & 3;
#pragma unroll
    for (int mt = 0; mt < 4; mt++) {
#pragma unroll
        for (int half = 0; half < 2; half++) {
            int c = mwarp + mt * 16 + gid + half * 8;
            float* dst = outp + ((size_t)b * C + c) * HW + p0;
#pragma unroll
            for (int nt = 0; nt < 2; nt++) {
                int col = nwarp + nt * 8 + 2 * tig;
                *(float2*)(dst + col) = make_float2(acc[mt * 2 + nt][half * 2],
                                                    acc[mt * 2 + nt][half * 2 + 1]);
            }
        }
    }
}

extern "C" void kernel_launch(void* const* d_in, const int* in_sizes, int n_in,
                              void* d_out, int out_size)
{
    const float* x     = (const float*)d_in[0];
    const float* wq    = (const float*)d_in[1];
    const float* wk    = (const float*)d_in[2];
    const float* wv    = (const float*)d_in[3];
    const float* wproj = (const float*)d_in[4];
    float* outp = (float*)d_out;

    cudaFuncSetAttribute(attn_kernel,
                         cudaFuncAttributeMaxDynamicSharedMemorySize, ATTN_SMEM);
    cudaFuncSetAttribute(qkv_mma_kernel,
                         cudaFuncAttributeMaxDynamicSharedMemorySize, GEMM_SMEM);
    cudaFuncSetAttribute(proj_mma_kernel,
                         cudaFuncAttributeMaxDynamicSharedMemorySize, PROJ_SMEM);

    xsplit_kernel<<<dim3(HW / 32, C / 32, 3), 256>>>(x, wq, wk, wv, wproj);
    qkv_mma_kernel<<<dim3(NTILES, 3, BATCH), 256, GEMM_SMEM>>>();
    attn_kernel<<<dim3(W / TX, H / TY, HEADS * BATCH), 256, ATTN_SMEM>>>();
    proj_mma_kernel<<<dim3(2 * NTILES, BATCH), 256, PROJ_SMEM>>>(outp);
}

// round 16
// speedup vs baseline: 1.6436x; 1.0609x over previous
#include <cuda_runtime.h>
#include <cuda_fp16.h>
#include <cstdint>

#define BATCH 2
#define C 128
#define H 96
#define W 96
#define HEADS 4
#define DHEAD 32
#define PAD 2
#define INNER 128
#define HW (H * W)
#define HP (H + 2 * PAD)
#define WP (W + 2 * PAD)
#define NTILES (HW / 128)   // 72

typedef unsigned long long u64;

// fp32 scratch
__device__ float g_q[(size_t)BATCH * HW * INNER];            // [b][p][inner]
// plane-major k/v: [b][h][g(8)][yp][xp] float4 (padding stays zero)
__device__ float4 g_kpad4[(size_t)BATCH * HEADS * 8 * HP * WP];
__device__ float4 g_vpad4[(size_t)BATCH * HEADS * 8 * HP * WP];

// fp16 operand images, PRE-SWIZZLED: half (row, c) at row*128 + ((c>>3)^(row&7))*8 + (c&7)
__device__ __half g_xh[(size_t)BATCH * HW * C];              // rows = pixels
__device__ __half g_wh[4 * C * INNER];                       // rows = out-ch
__device__ __half g_oh[(size_t)BATCH * HW * INNER];          // rows = pixels

#define FFMA2(d, a, b) \
    asm("fma.rn.f32x2 %0, %1, %2, %0;" : "+l"(d) : "l"(a), "l"(b))
#define PACK2(d, s) \
    asm("mov.b64 %0, {%1, %1};" : "=l"(d) : "f"(s))

__device__ __forceinline__ uint32_t smem_u32(const void* p) {
    uint32_t a;
    asm("{ .reg .u64 t; cvta.to.shared.u64 t, %1; cvt.u32.u64 %0, t; }"
        : "=r"(a) : "l"(p));
    return a;
}

#define MBARRIER_INIT(mb, n) \
    asm volatile("mbarrier.init.shared.b64 [%0], %1;" :: "r"((uint32_t)(mb)), "r"((uint32_t)(n)) : "memory")
#define MBARRIER_EXPECT_TX(mb, bytes) \
    asm volatile("mbarrier.arrive.expect_tx.shared.b64 _, [%0], %1;" \
                 :: "r"((uint32_t)(mb)), "r"((uint32_t)(bytes)) : "memory")
#define MBARRIER_WAIT_PARITY(mb, ph) do {                                         \
    uint32_t _mb = (uint32_t)(mb); uint32_t _ph = (uint32_t)(ph); uint32_t _done; \
    asm volatile("{ .reg .pred p; mbarrier.try_wait.parity.acquire.cta.shared::cta.b64 p, [%1], %2; selp.b32 %0, 1, 0, p; }" \
                 : "=r"(_done) : "r"(_mb), "r"(_ph) : "memory");                  \
    if (!_done) {                                                                 \
        asm volatile("{ .reg .pred P1; WL_%=: mbarrier.try_wait.parity.acquire.cta.shared::cta.b64 P1, [%0], %1, 0x989680; @P1 bra.uni WD_%=; bra.uni WL_%=; WD_%=: }" \
                     :: "r"(_mb), "r"(_ph) : "memory");                           \
    } } while (0)

#define BULK_G2S(dst, src, bytes, mbar) \
    asm volatile("cp.async.bulk.shared::cluster.global.mbarrier::complete_tx::bytes [%0], [%1], %2, [%3];" \
        :: "r"((uint32_t)(dst)), "l"(src), "r"((uint32_t)(bytes)), "r"((uint32_t)(mbar)) : "memory")

// pack two f32 -> f16x2 reg, v0 in low half (memory element 0)
#define PACK_F16X2(res, v0, v1) \
    asm("cvt.rn.f16x2.f32 %0, %1, %2;" : "=r"(res) : "f"(v1), "f"(v0))

#define LDM_X4(r, addr) \
    asm volatile("ldmatrix.sync.aligned.m8n8.x4.shared.b16 {%0,%1,%2,%3}, [%4];" \
        : "=r"((r)[0]), "=r"((r)[1]), "=r"((r)[2]), "=r"((r)[3]) : "r"(addr))

#define MMA16816(d, a, bp) \
    asm volatile("mma.sync.aligned.m16n8k16.row.col.f32.f16.f16.f32 " \
        "{%0,%1,%2,%3}, {%4,%5,%6,%7}, {%8,%9}, {%0,%1,%2,%3};" \
        : "+f"((d)[0]), "+f"((d)[1]), "+f"((d)[2]), "+f"((d)[3]) \
        : "r"((a)[0]), "r"((a)[1]), "r"((a)[2]), "r"((a)[3]), \
          "r"((bp)[0]), "r"((bp)[1]))

// GEMM smem: dense 32KB tiles (256B rows, XOR-swizzled images) + mbarrier
#define TILE 32768
#define HTILE 16384
#define GEMM_SMEM (2 * TILE + 16)           // qkv: X + W
#define PROJ_SMEM (HTILE + TILE + 16)       // proj: 16K O-tile + W

// swizzled half-index within a row: chunk (c>>3) ^ (row&7), sub c&7
__device__ __forceinline__ int sw_idx(int row, int c) {
    return (((c >> 3) ^ (row & 7)) << 3) + (c & 7);
}

// ---------------------------------------------------------------------------
// Kernel A: z<2: split x -> g_xh (fp16 [p][c], swizzled); z==2: bake weights
// ---------------------------------------------------------------------------
__global__ __launch_bounds__(256) void xsplit_kernel(
    const float* __restrict__ x,  const float* __restrict__ wq,
    const float* __restrict__ wk, const float* __restrict__ wv,
    const float* __restrict__ wp)
{
    if (blockIdx.z == 2) {
        int idx = (blockIdx.y * gridDim.x + blockIdx.x) * 256 + threadIdx.x;
        if (idx < 4 * C * INNER) {
            int mat = idx >> 14, e = idx & 16383;
            const float* __restrict__ src =
                (mat == 0) ? wq : (mat == 1) ? wk : (mat == 2) ? wv : wp;
            float w = src[e];
            int o = e >> 7, c = e & 127;
            g_wh[(size_t)mat * 16384 + o * 128 + sw_idx(o, c)] = __float2half_rn(w);
        }
        return;
    }
    __shared__ float t[32][33];
    const int p0 = blockIdx.x * 32, c0 = blockIdx.y * 32, b = blockIdx.z;
    const int tl = threadIdx.x & 31, th = threadIdx.x >> 5;
#pragma unroll
    for (int i = 0; i < 4; i++) {
        int c = th + i * 8;
        t[c][tl] = x[((size_t)b * C + c0 + c) * HW + p0 + tl];
    }
    __syncthreads();
#pragma unroll
    for (int i = 0; i < 4; i++) {
        int p = th + i * 8;
        int P = p0 + p, c = c0 + tl;
        g_xh[((size_t)b * HW + P) * C + sw_idx(P, c)] = __float2half_rn(t[tl][p]);
    }
}

// ---------------------------------------------------------------------------
// HMMA mainloop on dense 256B-row tiles with XOR swizzle (full 128x128)
// ---------------------------------------------------------------------------
__device__ __forceinline__ void mma_tiles(
    uint32_t Abase, uint32_t Bbase, int lane, int mwarp, int nwarp,
    float (*acc)[4])
{
    const int xr = lane & 7;
    const uint32_t arowb = Abase + (uint32_t)(mwarp + (lane & 15)) * 256;
    const int ac0 = (lane >> 4) & 1;
    const uint32_t browb = Bbase
                         + (uint32_t)(nwarp + ((lane >> 4) << 3) + (lane & 7)) * 256;
    const int bc0 = (lane >> 3) & 1;
#pragma unroll
    for (int k0 = 0; k0 < 8; k0++) {
        const uint32_t aoff = (uint32_t)(((k0 * 2 + ac0) ^ xr) << 4);
        const uint32_t boff = (uint32_t)(((k0 * 2 + bc0) ^ xr) << 4);
        uint32_t a[4][4], bq[2][4];
#pragma unroll
        for (int mt = 0; mt < 4; mt++)
            LDM_X4(a[mt], arowb + mt * (16 * 256) + aoff);
#pragma unroll
        for (int n2 = 0; n2 < 2; n2++)
            LDM_X4(bq[n2], browb + n2 * (16 * 256) + boff);
#pragma unroll
        for (int mt = 0; mt < 4; mt++)
#pragma unroll
            for (int nt = 0; nt < 4; nt++)
                MMA16816(acc[mt * 4 + nt], a[mt], &bq[nt >> 1][(nt & 1) * 2]);
    }
}

// Variant for 64-row B tile: warp covers 16 B-rows (one ldmatrix x4 per k0)
__device__ __forceinline__ void mma_tiles_n64(
    uint32_t Abase, uint32_t Bbase, int lane, int mwarp, int nwarp,
    float (*acc)[4])
{
    const int xr = lane & 7;
    const uint32_t arowb = Abase + (uint32_t)(mwarp + (lane & 15)) * 256;
    const int ac0 = (lane >> 4) & 1;
    const uint32_t browb = Bbase
                         + (uint32_t)(nwarp + ((lane >> 4) << 3) + (lane & 7)) * 256;
    const int bc0 = (lane >> 3) & 1;
#pragma unroll
    for (int k0 = 0; k0 < 8; k0++) {
        const uint32_t aoff = (uint32_t)(((k0 * 2 + ac0) ^ xr) << 4);
        const uint32_t boff = (uint32_t)(((k0 * 2 + bc0) ^ xr) << 4);
        uint32_t a[4][4], bq[4];
#pragma unroll
        for (int mt = 0; mt < 4; mt++)
            LDM_X4(a[mt], arowb + mt * (16 * 256) + aoff);
        LDM_X4(bq, browb + boff);
#pragma unroll
        for (int mt = 0; mt < 4; mt++)
#pragma unroll
            for (int nt = 0; nt < 2; nt++)
                MMA16816(acc[mt * 2 + nt], a[mt], &bq[nt * 2]);
    }
}

// ---------------------------------------------------------------------------
// Kernel 1: QKV. D[p][o] = Xh[p][c] * Wh[o][c].  Single fp16 pass.
// ---------------------------------------------------------------------------
__global__ __launch_bounds__(256, 2) void qkv_mma_kernel()
{
    extern __shared__ char sm[];
    const uint32_t smb = smem_u32(sm);
    const int tid = threadIdx.x, wid = tid >> 5, lane = tid & 31;
    const int pb = blockIdx.x, mat = blockIdx.y, b = blockIdx.z;
    const int p0 = pb * 128;

    const uint32_t S0 = smb, S1 = smb + TILE, MB0 = smb + 2 * TILE;

    if (tid == 0) MBARRIER_INIT(MB0, 2);
    __syncthreads();
    if (tid == 0) {
        MBARRIER_EXPECT_TX(MB0, TILE);
        BULK_G2S(S0, g_xh + ((size_t)b * HW + p0) * C, TILE, MB0);
    } else if (tid == 32) {
        MBARRIER_EXPECT_TX(MB0, TILE);
        BULK_G2S(S1, g_wh + mat * 16384, TILE, MB0);
    }

    float acc[16][4];
#pragma unroll
    for (int i = 0; i < 16; i++)
#pragma unroll
        for (int j = 0; j < 4; j++) acc[i][j] = 0.f;

    const int mwarp = (wid >> 2) * 64, nwarp = (wid & 3) * 32;

    MBARRIER_WAIT_PARITY(MB0, 0);
    mma_tiles(S0, S1, lane, mwarp, nwarp, acc);

    const int gid = lane >> 2, tig = lane & 3;
#pragma unroll
    for (int mt = 0; mt < 4; mt++) {
#pragma unroll
        for (int half = 0; half < 2; half++) {
            int r = mwarp + mt * 16 + gid + half * 8;
            int p = p0 + r;
            if (mat == 0) {
                float* dst = g_q + ((size_t)b * HW + p) * INNER;
#pragma unroll
                for (int nt = 0; nt < 4; nt++) {
                    int o = nwarp + nt * 8 + 2 * tig;
                    *(float2*)(dst + o) = make_float2(acc[mt * 4 + nt][half * 2],
                                                      acc[mt * 4 + nt][half * 2 + 1]);
                }
            } else {
                int yy = p / W, xx = p - yy * W;
                float4* base = (mat == 1) ? g_kpad4 : g_vpad4;
#pragma unroll
                for (int nt = 0; nt < 4; nt++) {
                    int c = nwarp + nt * 8 + 2 * tig;
                    int h = c >> 5, g = (c >> 2) & 7, sub = c & 3;
                    float* dst = (float*)(base
                        + ((((size_t)(b * HEADS + h) * 8 + g) * HP + yy + PAD) * WP
                           + xx + PAD)) + sub;
                    *(float2*)dst = make_float2(acc[mt * 4 + nt][half * 2],
                                                acc[mt * 4 + nt][half * 2 + 1]);
                }
            }
        }
    }
}

// ---------------------------------------------------------------------------
// Kernel 2: window attention (fused one-pass), bulk-staged halo.
// ---------------------------------------------------------------------------
#define TX 32
#define TY 8
#define PWT (TX + 4)     // 36
#define PHT (TY + 4)     // 12
#define DGS 433
#define ATTN_SMEM (2 * 8 * DGS * 16 + 16)   // + mbarrier

__global__ __launch_bounds__(256, 2) void attn_kernel()
{
    extern __shared__ float4 sm4[];
    float4* ks4 = sm4;
    float4* vs4 = sm4 + 8 * DGS;
    const uint32_t smbk = smem_u32(ks4);
    const uint32_t smbv = smem_u32(vs4);
    const uint32_t MB = smbk + 2 * 8 * DGS * 16;

    const int t  = threadIdx.x;
    const int x0 = blockIdx.x * TX;
    const int y0 = blockIdx.y * TY;
    const int h  = blockIdx.z & 3;
    const int b  = blockIdx.z >> 2;

    if (t == 0) MBARRIER_INIT(MB, 192);
    __syncthreads();

    // 192 bulk copies: 2(kv) x 8 planes x 12 rows, 576B each
    if (t < 192) {
        int kv = t >= 96;
        int j  = t - kv * 96;
        int pl = j / 12, py = j - pl * 12;
        int gsrc = (pl & 1) * 4 + (pl >> 1);
        const float4* src = (kv ? g_vpad4 : g_kpad4)
            + (((size_t)(b * HEADS + h) * 8 + gsrc) * HP + y0 + py) * WP + x0;
        uint32_t dst = (kv ? smbv : smbk) + (uint32_t)(pl * DGS + py * PWT) * 16;
        MBARRIER_EXPECT_TX(MB, 576);
        BULK_G2S(dst, src, 576, MB);
    }

    const int hh   = t & 1;          // d-half
    const int pair = t >> 1;         // 0..127
    const int tx2  = pair & 15;
    const int ty   = pair >> 4;
    const int p0p  = (y0 + ty) * W + x0 + 2 * tx2;

    const float scale = 0.17677669529663687f;  // 1/sqrt(32)
    float q0f[16], q1f[16];
    {
        const float* qp0 = g_q + ((size_t)b * HW + p0p) * INNER + h * DHEAD + hh * 16;
        const float* qp1 = qp0 + INNER;
#pragma unroll
        for (int i = 0; i < 4; i++) {
            float4 v0 = *(const float4*)(qp0 + i * 4);
            float4 v1 = *(const float4*)(qp1 + i * 4);
            q0f[4 * i] = v0.x * scale; q0f[4 * i + 1] = v0.y * scale;
            q0f[4 * i + 2] = v0.z * scale; q0f[4 * i + 3] = v0.w * scale;
            q1f[4 * i] = v1.x * scale; q1f[4 * i + 1] = v1.y * scale;
            q1f[4 * i + 2] = v1.z * scale; q1f[4 * i + 3] = v1.w * scale;
        }
    }
    u64 q0[8], q1[8];
#pragma unroll
    for (int i = 0; i < 8; i++) {
        q0[i] = *(u64*)&q0f[2 * i];
        q1[i] = *(u64*)&q1f[2 * i];
    }

    MBARRIER_WAIT_PARITY(MB, 0);
    __syncthreads();

    u64 o0[8], o1[8];
#pragma unroll
    for (int i = 0; i < 8; i++) { o0[i] = 0ull; o1[i] = 0ull; }
    float sum0 = 0.f, sum1 = 0.f;

#pragma unroll
    for (int di = 0; di < 5; di++) {
#pragma unroll
        for (int djj = 0; djj < 6; djj++) {
            const int pixi = (ty + di) * PWT + 2 * tx2 + djj;

            u64 a0 = 0ull, a1 = 0ull, b0 = 0ull, b1 = 0ull;
#pragma unroll
            for (int dgl = 0; dgl < 4; dgl++) {
                ulonglong2 kq = *(const ulonglong2*)&ks4[(dgl * 2 + hh) * DGS + pixi];
                FFMA2(a0, q0[2 * dgl], kq.x);
                FFMA2(a1, q0[2 * dgl + 1], kq.y);
                FFMA2(b0, q1[2 * dgl], kq.x);
                FFMA2(b1, q1[2 * dgl + 1], kq.y);
            }
            float2 fa0 = *(float2*)&a0, fa1 = *(float2*)&a1;
            float2 fb0 = *(float2*)&b0, fb1 = *(float2*)&b1;
            float p0s = (fa0.x + fa0.y) + (fa1.x + fa1.y);
            float p1s = (fb0.x + fb0.y) + (fb1.x + fb1.y);
            p0s += __shfl_xor_sync(0xffffffffu, p0s, 1);
            p1s += __shfl_xor_sync(0xffffffffu, p1s, 1);

            u64 w0 = 0ull, w1 = 0ull;
            if (djj < 5) {
                float e = __expf(p0s);
                sum0 += e;
                PACK2(w0, e);
            }
            if (djj > 0) {
                float e = __expf(p1s);
                sum1 += e;
                PACK2(w1, e);
            }

#pragma unroll
            for (int dgl = 0; dgl < 4; dgl++) {
                ulonglong2 vq = *(const ulonglong2*)&vs4[(dgl * 2 + hh) * DGS + pixi];
                if (djj < 5) {
                    FFMA2(o0[2 * dgl], w0, vq.x);
                    FFMA2(o0[2 * dgl + 1], w0, vq.y);
                }
                if (djj > 0) {
                    FFMA2(o1[2 * dgl], w1, vq.x);
                    FFMA2(o1[2 * dgl + 1], w1, vq.y);
                }
            }
        }
    }

    const float inv0 = 1.f / sum0, inv1 = 1.f / sum1;

    // store fp16, swizzled image: chunks (h*4+hh*2+{0,1}) ^ (P&7)
#pragma unroll
    for (int px = 0; px < 2; px++) {
        const u64* oo = px ? o1 : o0;
        const float inv = px ? inv1 : inv0;
        uint32_t hu[8];
#pragma unroll
        for (int i = 0; i < 8; i++) {
            float2 f = *(float2*)&oo[i];
            PACK_F16X2(hu[i], f.x * inv, f.y * inv);
        }
        const int P = p0p + px;
        __half* rowp = g_oh + ((size_t)b * HW + P) * INNER;
        const int cb = h * 4 + hh * 2, xr = P & 7;
        *(uint4*)(rowp + ((cb ^ xr) << 3))       = make_uint4(hu[0], hu[1], hu[2], hu[3]);
        *(uint4*)(rowp + (((cb + 1) ^ xr) << 3)) = make_uint4(hu[4], hu[5], hu[6], hu[7]);
    }
}

// ---------------------------------------------------------------------------
// Kernel 3: proj, 64-pixel tiles, single fp16 pass.
// D[c][p] = Wph[c][i] * Oh[p][i]. grid (2*NTILES, BATCH).
// ---------------------------------------------------------------------------
__global__ __launch_bounds__(256, 2) void proj_mma_kernel(float* __restrict__ outp)
{
    extern __shared__ char sm[];
    const uint32_t smb = smem_u32(sm);
    const int tid = threadIdx.x, wid = tid >> 5, lane = tid & 31;
    const int pb = blockIdx.x, b = blockIdx.y;
    const int p0 = pb * 64;

    const uint32_t SB = smb;                    // Oh tile, 64 rows = 16KB
    const uint32_t S1 = smb + HTILE;            // Wh, 32KB
    const uint32_t MB0 = smb + HTILE + TILE;

    if (tid == 0) MBARRIER_INIT(MB0, 2);
    __syncthreads();
    if (tid == 0) {
        MBARRIER_EXPECT_TX(MB0, HTILE);
        BULK_G2S(SB, g_oh + ((size_t)b * HW + p0) * INNER, HTILE, MB0);
    } else if (tid == 32) {
        MBARRIER_EXPECT_TX(MB0, TILE);
        BULK_G2S(S1, g_wh + 3 * 16384, TILE, MB0);
    }

    float acc[8][4];
#pragma unroll
    for (int i = 0; i < 8; i++)
#pragma unroll
        for (int j = 0; j < 4; j++) acc[i][j] = 0.f;

    const int mwarp = (wid >> 2) * 64, nwarp = (wid & 3) * 16;

    MBARRIER_WAIT_PARITY(MB0, 0);
    mma_tiles_n64(S1, SB, lane, mwarp, nwarp, acc);

    const int gid = lane >> 2, tig = lane & 3;
#pragma unroll
    for (int mt = 0; mt < 4; mt++) {
#pragma unroll
        for (int half = 0; half < 2; half++) {
            int c = mwarp + mt * 16 + gid + half * 8;
            float* dst = outp + ((size_t)b * C + c) * HW + p0;
#pragma unroll
            for (int nt = 0; nt < 2; nt++) {
                int col = nwarp + nt * 8 + 2 * tig;
                *(float2*)(dst + col) = make_float2(acc[mt * 2 + nt][half * 2],
                                                    acc[mt * 2 + nt][half * 2 + 1]);
            }
        }
    }
}

extern "C" void kernel_launch(void* const* d_in, const int* in_sizes, int n_in,
                              void* d_out, int out_size)
{
    const float* x     = (const float*)d_in[0];
    const float* wq    = (const float*)d_in[1];
    const float* wk    = (const float*)d_in[2];
    const float* wv    = (const float*)d_in[3];
    const float* wproj = (const float*)d_in[4];
    float* outp = (float*)d_out;

    cudaFuncSetAttribute(attn_kernel,
                         cudaFuncAttributeMaxDynamicSharedMemorySize, ATTN_SMEM);
    cudaFuncSetAttribute(qkv_mma_kernel,
                         cudaFuncAttributeMaxDynamicSharedMemorySize, GEMM_SMEM);
    cudaFuncSetAttribute(proj_mma_kernel,
                         cudaFuncAttributeMaxDynamicSharedMemorySize, PROJ_SMEM);

    xsplit_kernel<<<dim3(HW / 32, C / 32, 3), 256>>>(x, wq, wk, wv, wproj);
    qkv_mma_kernel<<<dim3(NTILES, 3, BATCH), 256, GEMM_SMEM>>>();
    attn_kernel<<<dim3(W / TX, H / TY, HEADS * BATCH), 256, ATTN_SMEM>>>();
    proj_mma_kernel<<<dim3(2 * NTILES, BATCH), 256, PROJ_SMEM>>>(outp);
}

// round 17
// speedup vs baseline: 1.6897x; 1.0280x over previous
#include <cuda_runtime.h>
#include <cuda_fp16.h>
#include <cstdint>

#define BATCH 2
#define C 128
#define H 96
#define W 96
#define HEADS 4
#define DHEAD 32
#define PAD 2
#define INNER 128
#define HW (H * W)
#define HP (H + 2 * PAD)
#define WP (W + 2 * PAD)
#define NTILES (HW / 128)   // 72

typedef unsigned long long u64;

// fp32 scratch
__device__ float g_q[(size_t)BATCH * HW * INNER];            // [b][p][inner]
// plane-major k/v: [b][h][g(8)][yp][xp] float4 (padding stays zero)
__device__ float4 g_kpad4[(size_t)BATCH * HEADS * 8 * HP * WP];
__device__ float4 g_vpad4[(size_t)BATCH * HEADS * 8 * HP * WP];

// fp16 operand images, PRE-SWIZZLED: half (row, c) at row*128 + ((c>>3)^(row&7))*8 + (c&7)
__device__ __half g_xh[(size_t)BATCH * HW * C];              // rows = pixels
__device__ __half g_wh[4 * C * INNER];                       // rows = out-ch
__device__ __half g_oh[(size_t)BATCH * HW * INNER];          // rows = pixels

#define FFMA2(d, a, b) \
    asm("fma.rn.f32x2 %0, %1, %2, %0;" : "+l"(d) : "l"(a), "l"(b))
#define PACK2(d, s) \
    asm("mov.b64 %0, {%1, %1};" : "=l"(d) : "f"(s))

__device__ __forceinline__ uint32_t smem_u32(const void* p) {
    uint32_t a;
    asm("{ .reg .u64 t; cvta.to.shared.u64 t, %1; cvt.u32.u64 %0, t; }"
        : "=r"(a) : "l"(p));
    return a;
}

#define MBARRIER_INIT(mb, n) \
    asm volatile("mbarrier.init.shared.b64 [%0], %1;" :: "r"((uint32_t)(mb)), "r"((uint32_t)(n)) : "memory")
#define MBARRIER_EXPECT_TX(mb, bytes) \
    asm volatile("mbarrier.arrive.expect_tx.shared.b64 _, [%0], %1;" \
                 :: "r"((uint32_t)(mb)), "r"((uint32_t)(bytes)) : "memory")
#define MBARRIER_WAIT_PARITY(mb, ph) do {                                         \
    uint32_t _mb = (uint32_t)(mb); uint32_t _ph = (uint32_t)(ph); uint32_t _done; \
    asm volatile("{ .reg .pred p; mbarrier.try_wait.parity.acquire.cta.shared::cta.b64 p, [%1], %2; selp.b32 %0, 1, 0, p; }" \
                 : "=r"(_done) : "r"(_mb), "r"(_ph) : "memory");                  \
    if (!_done) {                                                                 \
        asm volatile("{ .reg .pred P1; WL_%=: mbarrier.try_wait.parity.acquire.cta.shared::cta.b64 P1, [%0], %1, 0x989680; @P1 bra.uni WD_%=; bra.uni WL_%=; WD_%=: }" \
                     :: "r"(_mb), "r"(_ph) : "memory");                           \
    } } while (0)

#define BULK_G2S(dst, src, bytes, mbar) \
    asm volatile("cp.async.bulk.shared::cluster.global.mbarrier::complete_tx::bytes [%0], [%1], %2, [%3];" \
        :: "r"((uint32_t)(dst)), "l"(src), "r"((uint32_t)(bytes)), "r"((uint32_t)(mbar)) : "memory")

// pack two f32 -> f16x2 reg, v0 in low half (memory element 0)
#define PACK_F16X2(res, v0, v1) \
    asm("cvt.rn.f16x2.f32 %0, %1, %2;" : "=r"(res) : "f"(v1), "f"(v0))

#define LDM_X4(r, addr) \
    asm volatile("ldmatrix.sync.aligned.m8n8.x4.shared.b16 {%0,%1,%2,%3}, [%4];" \
        : "=r"((r)[0]), "=r"((r)[1]), "=r"((r)[2]), "=r"((r)[3]) : "r"(addr))

#define MMA16816(d, a, bp) \
    asm volatile("mma.sync.aligned.m16n8k16.row.col.f32.f16.f16.f32 " \
        "{%0,%1,%2,%3}, {%4,%5,%6,%7}, {%8,%9}, {%0,%1,%2,%3};" \
        : "+f"((d)[0]), "+f"((d)[1]), "+f"((d)[2]), "+f"((d)[3]) \
        : "r"((a)[0]), "r"((a)[1]), "r"((a)[2]), "r"((a)[3]), \
          "r"((bp)[0]), "r"((bp)[1]))

// GEMM smem: dense 32KB tiles (256B rows, XOR-swizzled images) + slice mbarriers
#define TILE 32768
#define HTILE 16384
#define GEMM_SMEM (2 * TILE + 64)           // qkv: X + W + 6 barriers
#define PROJ_SMEM (HTILE + TILE + 64)       // proj: O tile + W + 6 barriers

// swizzled half-index within a row: chunk (c>>3) ^ (row&7), sub c&7
__device__ __forceinline__ int sw_idx(int row, int c) {
    return (((c >> 3) ^ (row & 7)) << 3) + (c & 7);
}

// ---------------------------------------------------------------------------
// Kernel A: z<2: split x -> g_xh (fp16 [p][c], swizzled, u32-packed stores);
//           z==2: bake weights -> fp16 [mat][o][c]
// ---------------------------------------------------------------------------
__global__ __launch_bounds__(256) void xsplit_kernel(
    const float* __restrict__ x,  const float* __restrict__ wq,
    const float* __restrict__ wk, const float* __restrict__ wv,
    const float* __restrict__ wp)
{
    if (blockIdx.z == 2) {
        int idx = (blockIdx.y * gridDim.x + blockIdx.x) * 256 + threadIdx.x;
        if (idx < 4 * C * INNER) {
            int mat = idx >> 14, e = idx & 16383;
            const float* __restrict__ src =
                (mat == 0) ? wq : (mat == 1) ? wk : (mat == 2) ? wv : wp;
            float w = src[e];
            int o = e >> 7, c = e & 127;
            g_wh[(size_t)mat * 16384 + o * 128 + sw_idx(o, c)] = __float2half_rn(w);
        }
        return;
    }
    __shared__ float t[32][33];
    const int p0 = blockIdx.x * 32, c0 = blockIdx.y * 32, b = blockIdx.z;
    const int tl = threadIdx.x & 31, th = threadIdx.x >> 5;
#pragma unroll
    for (int i = 0; i < 4; i++) {
        int c = th + i * 8;
        t[c][tl] = x[((size_t)b * C + c0 + c) * HW + p0 + tl];
    }
    __syncthreads();
    const int cp = threadIdx.x & 15;        // channel pair
#pragma unroll
    for (int i = 0; i < 2; i++) {
        int pi = (threadIdx.x >> 4) + i * 16;   // 0..31
        int P = p0 + pi, c = c0 + 2 * cp;
        uint32_t u;
        PACK_F16X2(u, t[2 * cp][pi], t[2 * cp + 1][pi]);
        *(uint32_t*)(g_xh + ((size_t)b * HW + P) * C + sw_idx(P, c)) = u;
    }
}

// ---------------------------------------------------------------------------
// HMMA mainloop on dense 256B-row tiles with XOR swizzle (full 128x128)
// ---------------------------------------------------------------------------
__device__ __forceinline__ void mma_tiles(
    uint32_t Abase, uint32_t Bbase, int lane, int mwarp, int nwarp,
    float (*acc)[4])
{
    const int xr = lane & 7;
    const uint32_t arowb = Abase + (uint32_t)(mwarp + (lane & 15)) * 256;
    const int ac0 = (lane >> 4) & 1;
    const uint32_t browb = Bbase
                         + (uint32_t)(nwarp + ((lane >> 4) << 3) + (lane & 7)) * 256;
    const int bc0 = (lane >> 3) & 1;
#pragma unroll
    for (int k0 = 0; k0 < 8; k0++) {
        const uint32_t aoff = (uint32_t)(((k0 * 2 + ac0) ^ xr) << 4);
        const uint32_t boff = (uint32_t)(((k0 * 2 + bc0) ^ xr) << 4);
        uint32_t a[4][4], bq[2][4];
#pragma unroll
        for (int mt = 0; mt < 4; mt++)
            LDM_X4(a[mt], arowb + mt * (16 * 256) + aoff);
#pragma unroll
        for (int n2 = 0; n2 < 2; n2++)
            LDM_X4(bq[n2], browb + n2 * (16 * 256) + boff);
#pragma unroll
        for (int mt = 0; mt < 4; mt++)
#pragma unroll
            for (int nt = 0; nt < 4; nt++)
                MMA16816(acc[mt * 4 + nt], a[mt], &bq[nt >> 1][(nt & 1) * 2]);
    }
}

// Variant for 64-row B tile: warp covers 16 B-rows
__device__ __forceinline__ void mma_tiles_n64(
    uint32_t Abase, uint32_t Bbase, int lane, int mwarp, int nwarp,
    float (*acc)[4])
{
    const int xr = lane & 7;
    const uint32_t arowb = Abase + (uint32_t)(mwarp + (lane & 15)) * 256;
    const int ac0 = (lane >> 4) & 1;
    const uint32_t browb = Bbase
                         + (uint32_t)(nwarp + ((lane >> 4) << 3) + (lane & 7)) * 256;
    const int bc0 = (lane >> 3) & 1;
#pragma unroll
    for (int k0 = 0; k0 < 8; k0++) {
        const uint32_t aoff = (uint32_t)(((k0 * 2 + ac0) ^ xr) << 4);
        const uint32_t boff = (uint32_t)(((k0 * 2 + bc0) ^ xr) << 4);
        uint32_t a[4][4], bq[4];
#pragma unroll
        for (int mt = 0; mt < 4; mt++)
            LDM_X4(a[mt], arowb + mt * (16 * 256) + aoff);
        LDM_X4(bq, browb + boff);
#pragma unroll
        for (int mt = 0; mt < 4; mt++)
#pragma unroll
            for (int nt = 0; nt < 2; nt++)
                MMA16816(acc[mt * 2 + nt], a[mt], &bq[nt * 2]);
    }
}

// ---------------------------------------------------------------------------
// Kernel 1: QKV. D[p][o] = Xh[p][c] * Wh[o][c].  Slice-barrier staging:
//  X halves (rows 0-63 / 64-127) -> MB[0..1]; W quarters (32 rows) -> MB[2..5]
// ---------------------------------------------------------------------------
__global__ __launch_bounds__(256, 2) void qkv_mma_kernel()
{
    extern __shared__ char sm[];
    const uint32_t smb = smem_u32(sm);
    const int tid = threadIdx.x, wid = tid >> 5, lane = tid & 31;
    const int pb = blockIdx.x, mat = blockIdx.y, b = blockIdx.z;
    const int p0 = pb * 128;

    const uint32_t S0 = smb, S1 = smb + TILE, MB = smb + 2 * TILE;

    if (tid == 0) {
#pragma unroll
        for (int i = 0; i < 6; i++) MBARRIER_INIT(MB + i * 8, 1);
    }
    __syncthreads();

    const __half* xsrc = g_xh + ((size_t)b * HW + p0) * C;
    const __half* wsrc = g_wh + mat * 16384;
    if (lane == 0 && wid < 6) {
        if (wid < 2) {
            MBARRIER_EXPECT_TX(MB + wid * 8, HTILE);
            BULK_G2S(S0 + wid * HTILE, xsrc + wid * 8192, HTILE, MB + wid * 8);
        } else {
            int qrt = wid - 2;
            MBARRIER_EXPECT_TX(MB + wid * 8, 8192);
            BULK_G2S(S1 + qrt * 8192, wsrc + qrt * 4096, 8192, MB + wid * 8);
        }
    }

    float acc[16][4];
#pragma unroll
    for (int i = 0; i < 16; i++)
#pragma unroll
        for (int j = 0; j < 4; j++) acc[i][j] = 0.f;

    const int mi = wid >> 2, ni = wid & 3;
    const int mwarp = mi * 64, nwarp = ni * 32;

    MBARRIER_WAIT_PARITY(MB + mi * 8, 0);
    MBARRIER_WAIT_PARITY(MB + 16 + ni * 8, 0);
    mma_tiles(S0, S1, lane, mwarp, nwarp, acc);

    const int gid = lane >> 2, tig = lane & 3;
#pragma unroll
    for (int mt = 0; mt < 4; mt++) {
#pragma unroll
        for (int half = 0; half < 2; half++) {
            int r = mwarp + mt * 16 + gid + half * 8;
            int p = p0 + r;
            if (mat == 0) {
                float* dst = g_q + ((size_t)b * HW + p) * INNER;
#pragma unroll
                for (int nt = 0; nt < 4; nt++) {
                    int o = nwarp + nt * 8 + 2 * tig;
                    *(float2*)(dst + o) = make_float2(acc[mt * 4 + nt][half * 2],
                                                      acc[mt * 4 + nt][half * 2 + 1]);
                }
            } else {
                int yy = p / W, xx = p - yy * W;
                float4* base = (mat == 1) ? g_kpad4 : g_vpad4;
#pragma unroll
                for (int nt = 0; nt < 4; nt++) {
                    int c = nwarp + nt * 8 + 2 * tig;
                    int h = c >> 5, g = (c >> 2) & 7, sub = c & 3;
                    float* dst = (float*)(base
                        + ((((size_t)(b * HEADS + h) * 8 + g) * HP + yy + PAD) * WP
                           + xx + PAD)) + sub;
                    *(float2*)dst = make_float2(acc[mt * 4 + nt][half * 2],
                                                acc[mt * 4 + nt][half * 2 + 1]);
                }
            }
        }
    }
}

// ---------------------------------------------------------------------------
// Kernel 2: window attention (fused one-pass), bulk-staged halo.
// ---------------------------------------------------------------------------
#define TX 32
#define TY 8
#define PWT (TX + 4)     // 36
#define PHT (TY + 4)     // 12
#define DGS 433
#define ATTN_SMEM (2 * 8 * DGS * 16 + 16)   // + mbarrier

__global__ __launch_bounds__(256, 2) void attn_kernel()
{
    extern __shared__ float4 sm4[];
    float4* ks4 = sm4;
    float4* vs4 = sm4 + 8 * DGS;
    const uint32_t smbk = smem_u32(ks4);
    const uint32_t smbv = smem_u32(vs4);
    const uint32_t MB = smbk + 2 * 8 * DGS * 16;

    const int t  = threadIdx.x;
    const int x0 = blockIdx.x * TX;
    const int y0 = blockIdx.y * TY;
    const int h  = blockIdx.z & 3;
    const int b  = blockIdx.z >> 2;

    if (t == 0) MBARRIER_INIT(MB, 192);
    __syncthreads();

    // 192 bulk copies: 2(kv) x 8 planes x 12 rows, 576B each
    if (t < 192) {
        int kv = t >= 96;
        int j  = t - kv * 96;
        int pl = j / 12, py = j - pl * 12;
        int gsrc = (pl & 1) * 4 + (pl >> 1);
        const float4* src = (kv ? g_vpad4 : g_kpad4)
            + (((size_t)(b * HEADS + h) * 8 + gsrc) * HP + y0 + py) * WP + x0;
        uint32_t dst = (kv ? smbv : smbk) + (uint32_t)(pl * DGS + py * PWT) * 16;
        MBARRIER_EXPECT_TX(MB, 576);
        BULK_G2S(dst, src, 576, MB);
    }

    const int hh   = t & 1;          // d-half
    const int pair = t >> 1;         // 0..127
    const int tx2  = pair & 15;
    const int ty   = pair >> 4;
    const int p0p  = (y0 + ty) * W + x0 + 2 * tx2;

    const float scale = 0.17677669529663687f;  // 1/sqrt(32)
    float q0f[16], q1f[16];
    {
        const float* qp0 = g_q + ((size_t)b * HW + p0p) * INNER + h * DHEAD + hh * 16;
        const float* qp1 = qp0 + INNER;
#pragma unroll
        for (int i = 0; i < 4; i++) {
            float4 v0 = *(const float4*)(qp0 + i * 4);
            float4 v1 = *(const float4*)(qp1 + i * 4);
            q0f[4 * i] = v0.x * scale; q0f[4 * i + 1] = v0.y * scale;
            q0f[4 * i + 2] = v0.z * scale; q0f[4 * i + 3] = v0.w * scale;
            q1f[4 * i] = v1.x * scale; q1f[4 * i + 1] = v1.y * scale;
            q1f[4 * i + 2] = v1.z * scale; q1f[4 * i + 3] = v1.w * scale;
        }
    }
    u64 q0[8], q1[8];
#pragma unroll
    for (int i = 0; i < 8; i++) {
        q0[i] = *(u64*)&q0f[2 * i];
        q1[i] = *(u64*)&q1f[2 * i];
    }

    MBARRIER_WAIT_PARITY(MB, 0);
    __syncthreads();

    u64 o0[8], o1[8];
#pragma unroll
    for (int i = 0; i < 8; i++) { o0[i] = 0ull; o1[i] = 0ull; }
    float sum0 = 0.f, sum1 = 0.f;

#pragma unroll
    for (int di = 0; di < 5; di++) {
#pragma unroll
        for (int djj = 0; djj < 6; djj++) {
            const int pixi = (ty + di) * PWT + 2 * tx2 + djj;

            u64 a0 = 0ull, a1 = 0ull, b0 = 0ull, b1 = 0ull;
#pragma unroll
            for (int dgl = 0; dgl < 4; dgl++) {
                ulonglong2 kq = *(const ulonglong2*)&ks4[(dgl * 2 + hh) * DGS + pixi];
                FFMA2(a0, q0[2 * dgl], kq.x);
                FFMA2(a1, q0[2 * dgl + 1], kq.y);
                FFMA2(b0, q1[2 * dgl], kq.x);
                FFMA2(b1, q1[2 * dgl + 1], kq.y);
            }
            float2 fa0 = *(float2*)&a0, fa1 = *(float2*)&a1;
            float2 fb0 = *(float2*)&b0, fb1 = *(float2*)&b1;
            float p0s = (fa0.x + fa0.y) + (fa1.x + fa1.y);
            float p1s = (fb0.x + fb0.y) + (fb1.x + fb1.y);
            p0s += __shfl_xor_sync(0xffffffffu, p0s, 1);
            p1s += __shfl_xor_sync(0xffffffffu, p1s, 1);

            u64 w0 = 0ull, w1 = 0ull;
            if (djj < 5) {
                float e = __expf(p0s);
                sum0 += e;
                PACK2(w0, e);
            }
            if (djj > 0) {
                float e = __expf(p1s);
                sum1 += e;
                PACK2(w1, e);
            }

#pragma unroll
            for (int dgl = 0; dgl < 4; dgl++) {
                ulonglong2 vq = *(const ulonglong2*)&vs4[(dgl * 2 + hh) * DGS + pixi];
                if (djj < 5) {
                    FFMA2(o0[2 * dgl], w0, vq.x);
                    FFMA2(o0[2 * dgl + 1], w0, vq.y);
                }
                if (djj > 0) {
                    FFMA2(o1[2 * dgl], w1, vq.x);
                    FFMA2(o1[2 * dgl + 1], w1, vq.y);
                }
            }
        }
    }

    const float inv0 = 1.f / sum0, inv1 = 1.f / sum1;

    // store fp16, swizzled image: chunks (h*4+hh*2+{0,1}) ^ (P&7)
#pragma unroll
    for (int px = 0; px < 2; px++) {
        const u64* oo = px ? o1 : o0;
        const float inv = px ? inv1 : inv0;
        uint32_t hu[8];
#pragma unroll
        for (int i = 0; i < 8; i++) {
            float2 f = *(float2*)&oo[i];
            PACK_F16X2(hu[i], f.x * inv, f.y * inv);
        }
        const int P = p0p + px;
        __half* rowp = g_oh + ((size_t)b * HW + P) * INNER;
        const int cb = h * 4 + hh * 2, xr = P & 7;
        *(uint4*)(rowp + ((cb ^ xr) << 3))       = make_uint4(hu[0], hu[1], hu[2], hu[3]);
        *(uint4*)(rowp + (((cb + 1) ^ xr) << 3)) = make_uint4(hu[4], hu[5], hu[6], hu[7]);
    }
}

// ---------------------------------------------------------------------------
// Kernel 3: proj, 64-pixel tiles, slice-barrier staging.
// W halves (16KB) -> MB[0..1]; O quarters (16 rows, 4KB) -> MB[2..5]
// ---------------------------------------------------------------------------
__global__ __launch_bounds__(256, 2) void proj_mma_kernel(float* __restrict__ outp)
{
    extern __shared__ char sm[];
    const uint32_t smb = smem_u32(sm);
    const int tid = threadIdx.x, wid = tid >> 5, lane = tid & 31;
    const int pb = blockIdx.x, b = blockIdx.y;
    const int p0 = pb * 64;

    const uint32_t SB = smb;                    // Oh tile, 64 rows = 16KB
    const uint32_t S1 = smb + HTILE;            // Wh, 32KB
    const uint32_t MB = smb + HTILE + TILE;

    if (tid == 0) {
#pragma unroll
        for (int i = 0; i < 6; i++) MBARRIER_INIT(MB + i * 8, 1);
    }
    __syncthreads();

    const __half* osrc = g_oh + ((size_t)b * HW + p0) * INNER;
    const __half* wsrc = g_wh + 3 * 16384;
    if (lane == 0 && wid < 6) {
        if (wid < 2) {
            MBARRIER_EXPECT_TX(MB + wid * 8, HTILE);
            BULK_G2S(S1 + wid * HTILE, wsrc + wid * 8192, HTILE, MB + wid * 8);
        } else {
            int qrt = wid - 2;
            MBARRIER_EXPECT_TX(MB + wid * 8, 4096);
            BULK_G2S(SB + qrt * 4096, osrc + qrt * 2048, 4096, MB + wid * 8);
        }
    }

    float acc[8][4];
#pragma unroll
    for (int i = 0; i < 8; i++)
#pragma unroll
        for (int j = 0; j < 4; j++) acc[i][j] = 0.f;

    const int mi = wid >> 2, ni = wid & 3;
    const int mwarp = mi * 64, nwarp = ni * 16;

    MBARRIER_WAIT_PARITY(MB + mi * 8, 0);
    MBARRIER_WAIT_PARITY(MB + 16 + ni * 8, 0);
    mma_tiles_n64(S1, SB, lane, mwarp, nwarp, acc);

    const int gid = lane >> 2, tig = lane & 3;
#pragma unroll
    for (int mt = 0; mt < 4; mt++) {
#pragma unroll
        for (int half = 0; half < 2; half++) {
            int c = mwarp + mt * 16 + gid + half * 8;
            float* dst = outp + ((size_t)b * C + c) * HW + p0;
#pragma unroll
            for (int nt = 0; nt < 2; nt++) {
                int col = nwarp + nt * 8 + 2 * tig;
                *(float2*)(dst + col) = make_float2(acc[mt * 2 + nt][half * 2],
                                                    acc[mt * 2 + nt][half * 2 + 1]);
            }
        }
    }
}

extern "C" void kernel_launch(void* const* d_in, const int* in_sizes, int n_in,
                              void* d_out, int out_size)
{
    const float* x     = (const float*)d_in[0];
    const float* wq    = (const float*)d_in[1];
    const float* wk    = (const float*)d_in[2];
    const float* wv    = (const float*)d_in[3];
    const float* wproj = (const float*)d_in[4];
    float* outp = (float*)d_out;

    cudaFuncSetAttribute(attn_kernel,
                         cudaFuncAttributeMaxDynamicSharedMemorySize, ATTN_SMEM);
    cudaFuncSetAttribute(qkv_mma_kernel,
                         cudaFuncAttributeMaxDynamicSharedMemorySize, GEMM_SMEM);
    cudaFuncSetAttribute(proj_mma_kernel,
                         cudaFuncAttributeMaxDynamicSharedMemorySize, PROJ_SMEM);

    xsplit_kernel<<<dim3(HW / 32, C / 32, 3), 256>>>(x, wq, wk, wv, wproj);
    qkv_mma_kernel<<<dim3(NTILES, 3, BATCH), 256, GEMM_SMEM>>>();
    attn_kernel<<<dim3(W / TX, H / TY, HEADS * BATCH), 256, ATTN_SMEM>>>();
    proj_mma_kernel<<<dim3(2 * NTILES, BATCH), 256, PROJ_SMEM>>>(outp);
}